// round 4
// baseline (speedup 1.0000x reference)
#include <cuda_runtime.h>
#include <math.h>

#define NQ 11
#define NL 3
#define SDIM 2048          // 2^NQ
#define BB 8
#define AA 96
#define NSTATE (BB*AA)     // 768
#define FDIM 64

// Scratch (no cudaMalloc allowed): per-state final real amplitudes, pre-scaled by pool weight.
__device__ float g_scratch[NSTATE * SDIM];   // 6 MB
__device__ float g_stats[BB * 3];            // per-batch {sumR2, sumRcos, sumRsin}

// ---------------------------------------------------------------------------
// Kernel 1: one CTA per state n = b*96+a. Computes the per-state feature map
// angles f[11], then simulates the 11-qubit real statevector in shared memory
// (3 layers x (11 rotations + 10 param-CNOTs)), writes w_a * amps to scratch.
// ---------------------------------------------------------------------------
__global__ __launch_bounds__(256) void k1_state(
    const float* __restrict__ nf,   // [768,64]
    const float* __restrict__ W1,   // [64,100]
    const float* __restrict__ b1,   // [64]
    const float* __restrict__ W2,   // [11,64]
    const float* __restrict__ b2,   // [11]
    const float* __restrict__ rot,  // [3,11,3]
    const float* __restrict__ ent,  // [3,10]
    const float* __restrict__ pw)   // [11]
{
    __shared__ float amps[SDIM];
    __shared__ float hbuf[64];
    __shared__ float f[NQ];
    const int n   = blockIdx.x;
    const int tid = threadIdx.x;

    // --- feature preprocessor: h = relu(x @ W1[:, :64]^T + b1) (pad cols are zero) ---
    const float* x = nf + n * FDIM;
    if (tid < 64) {
        float acc = b1[tid];
        const float* w = W1 + tid * 100;
        #pragma unroll 8
        for (int k = 0; k < 64; k++) acc = fmaf(x[k], w[k], acc);
        hbuf[tid] = fmaxf(acc, 0.f);
    }
    // init statevector |0...0>
    for (int s = tid; s < SDIM; s += 256) amps[s] = 0.f;
    if (tid == 0) amps[0] = 1.f;
    __syncthreads();

    if (tid < NQ) {
        float acc = b2[tid];
        const float* w = W2 + tid * 64;
        #pragma unroll 8
        for (int k = 0; k < 64; k++) acc = fmaf(hbuf[k], w[k], acc);
        f[tid] = tanhf(acc);
    }
    __syncthreads();

    for (int l = 0; l < NL; l++) {
        // --- single-qubit rotations (real 2x2 matrices) ---
        for (int q = 0; q < NQ; q++) {
            const float fq = f[q];
            const float* r = rot + (l * NQ + q) * 3;
            float cx, sx, cy, sy, cz, sz;
            sincosf(0.5f * r[0] * fq, &sx, &cx);
            sincosf(0.5f * r[1] * fq, &sy, &cy);
            sincosf(0.5f * r[2] * fq, &sz, &cz);
            const float M00 = cx * cy * cz, M01 = -sx * sy * sz;
            const float M10 = sx * sy * cz, M11 =  cx * cy * sz;
            const int maskq = (1 << q) - 1;
            #pragma unroll
            for (int k = 0; k < 4; k++) {
                const int p  = tid + k * 256;              // 1024 pairs
                const int lo = ((p >> q) << (q + 1)) | (p & maskq);
                const int hi = lo | (1 << q);
                const float a = amps[lo], b = amps[hi];
                amps[lo] = fmaf(M00, a, M01 * b);
                amps[hi] = fmaf(M10, a, M11 * b);
            }
            __syncthreads();
        }
        // --- parameterized CNOTs: states with bit q==1 mix symmetrically with
        //     their bit-(q+1)-flipped partner (both have ctrl==1) ---
        for (int q = 0; q < NQ - 1; q++) {
            const float pm = 1.f / (1.f + expf(-ent[l * (NQ - 1) + q]));
            const int maskq = (1 << q) - 1;
            #pragma unroll
            for (int k = 0; k < 2; k++) {
                const int j  = tid + k * 256;              // 512 pairs
                const int s0 = ((j >> q) << (q + 2)) | (1 << q) | (j & maskq);
                const int s1 = s0 | (2 << q);
                const float a = amps[s0], b = amps[s1];
                amps[s0] = fmaf(pm, b - a, a);
                amps[s1] = fmaf(pm, a - b, b);
            }
            __syncthreads();
        }
    }

    // --- write pool-weighted amps (phase applied later, it's state-independent) ---
    const float wa = 1.f / (1.f + expf(-pw[(n % AA) % NQ]));
    float* dst = g_scratch + (size_t)n * SDIM;
    for (int s = tid; s < SDIM; s += 256) dst[s] = amps[s] * wa;
}

// ---------------------------------------------------------------------------
// Kernel 2: one CTA per batch b. R[b,s] = sum_a scratch[b,a,s]; accumulate
// sum R^2, sum R*cos(phi_s), sum R*sin(phi_s) with phi_s = bits(s)·Theta.
// ---------------------------------------------------------------------------
__global__ __launch_bounds__(256) void k2_pool(const float* __restrict__ msg) // [3,11,3]
{
    __shared__ float theta[NQ];
    __shared__ float red[3][256];
    const int b = blockIdx.x, tid = threadIdx.x;

    if (tid < NQ) {
        float t = 0.f;
        for (int l = 0; l < NL; l++)
            for (int c = 0; c < 3; c++)
                t += msg[(l * NQ + tid) * 3 + c];
        theta[tid] = t;
    }
    __syncthreads();

    float s2 = 0.f, sc = 0.f, ss = 0.f;
    for (int s = tid; s < SDIM; s += 256) {
        float R = 0.f;
        const float* base = g_scratch + (size_t)(b * AA) * SDIM + s;
        #pragma unroll 4
        for (int a = 0; a < AA; a++) R += base[(size_t)a * SDIM];
        float phi = 0.f;
        #pragma unroll
        for (int q = 0; q < NQ; q++) if ((s >> q) & 1) phi += theta[q];
        float cp, sp;
        sincosf(phi, &sp, &cp);
        s2 = fmaf(R, R, s2);
        sc = fmaf(R, cp, sc);
        ss = fmaf(R, sp, ss);
    }
    red[0][tid] = s2; red[1][tid] = sc; red[2][tid] = ss;
    __syncthreads();
    for (int st = 128; st > 0; st >>= 1) {
        if (tid < st) {
            red[0][tid] += red[0][tid + st];
            red[1][tid] += red[1][tid + st];
            red[2][tid] += red[2][tid + st];
        }
        __syncthreads();
    }
    if (tid == 0) {
        g_stats[b * 3 + 0] = red[0][0];
        g_stats[b * 3 + 1] = red[1][0];
        g_stats[b * 3 + 2] = red[2][0];
    }
}

// ---------------------------------------------------------------------------
// Kernel 3: single CTA. Build rep[8,22] and run the output MLP.
// ---------------------------------------------------------------------------
__global__ __launch_bounds__(256) void k3_mlp(
    const float* __restrict__ Wo1, const float* __restrict__ bo1,   // [256,22],[256]
    const float* __restrict__ Wo2, const float* __restrict__ bo2,   // [128,256],[128]
    const float* __restrict__ Wo3, const float* __restrict__ bo3,   // [64,128],[64]
    float* __restrict__ out)                                        // [8,64]
{
    __shared__ float rep[BB][22];
    __shared__ float h1s[BB][256];
    __shared__ float h2s[BB][128];
    const int tid = threadIdx.x;

    if (tid < BB) {
        const float s2 = g_stats[tid * 3 + 0];
        const float sc = g_stats[tid * 3 + 1];
        const float ss = g_stats[tid * 3 + 2];
        const float inv = 1.f / (fmaxf(sqrtf(s2), 1e-12f) * (float)SDIM);
        const float rm = sc * inv, im = ss * inv;
        for (int q = 0; q < NQ; q++) { rep[tid][q] = rm; rep[tid][NQ + q] = im; }
    }
    __syncthreads();

    {   // h1 = relu(rep @ Wo1^T + bo1): 256 outputs x 8 batches
        const float* w = Wo1 + tid * 22;
        const float bias = bo1[tid];
        for (int b = 0; b < BB; b++) {
            float a = bias;
            #pragma unroll
            for (int k = 0; k < 22; k++) a = fmaf(rep[b][k], w[k], a);
            h1s[b][tid] = fmaxf(a, 0.f);
        }
    }
    __syncthreads();

    if (tid < 128) {   // h2 = relu(h1 @ Wo2^T + bo2)
        const float* w = Wo2 + tid * 256;
        const float bias = bo2[tid];
        for (int b = 0; b < BB; b++) {
            float a = bias;
            #pragma unroll 8
            for (int k = 0; k < 256; k++) a = fmaf(h1s[b][k], w[k], a);
            h2s[b][tid] = fmaxf(a, 0.f);
        }
    }
    __syncthreads();

    if (tid < 64) {    // out = h2 @ Wo3^T + bo3
        const float* w = Wo3 + tid * 128;
        const float bias = bo3[tid];
        for (int b = 0; b < BB; b++) {
            float a = bias;
            #pragma unroll 8
            for (int k = 0; k < 128; k++) a = fmaf(h2s[b][k], w[k], a);
            out[b * 64 + tid] = a;
        }
    }
}

// ---------------------------------------------------------------------------
extern "C" void kernel_launch(void* const* d_in, const int* in_sizes, int n_in,
                              void* d_out, int out_size)
{
    const float* nf   = (const float*)d_in[0];
    // d_in[1] = edge_indices (int32) — unused by the math
    const float* W1   = (const float*)d_in[2];
    const float* b1   = (const float*)d_in[3];
    const float* W2   = (const float*)d_in[4];
    const float* b2   = (const float*)d_in[5];
    const float* rot  = (const float*)d_in[6];
    const float* ent  = (const float*)d_in[7];
    const float* msg  = (const float*)d_in[8];
    const float* pw   = (const float*)d_in[9];
    const float* Wo1  = (const float*)d_in[10];
    const float* bo1  = (const float*)d_in[11];
    const float* Wo2  = (const float*)d_in[12];
    const float* bo2  = (const float*)d_in[13];
    const float* Wo3  = (const float*)d_in[14];
    const float* bo3  = (const float*)d_in[15];
    float* out = (float*)d_out;

    k1_state<<<NSTATE, 256>>>(nf, W1, b1, W2, b2, rot, ent, pw);
    k2_pool<<<BB, 256>>>(msg);
    k3_mlp<<<1, 256>>>(Wo1, bo1, Wo2, bo2, Wo3, bo3, out);
}

// round 7
// speedup vs baseline: 4.4647x; 4.4647x over previous
#include <cuda_runtime.h>
#include <math.h>

#define NQ 11
#define NL 3
#define SDIM 2048          // 2^NQ
#define BB 8
#define AA 96
#define NSTATE (BB*AA)     // 768
#define FDIM 64
#define NG (NL*NQ)         // 33 rotation gates
#define NE (NL*(NQ-1))     // 30 CNOT gates
#define K2CH 8             // s-chunks per batch in k2

// Scratch (no cudaMalloc allowed)
__device__ float g_scratch[NSTATE * SDIM];       // 6 MB pool-weighted amps
__device__ float g_part[BB * K2CH * 3];          // partial {sumR2,sumRcos,sumRsin}

// ---------------------------------------------------------------------------
// Kernel 1: one CTA per state n = b*96+a. Gate matrices precomputed in shared
// (one __sincosf per thread instead of 99 accurate sincosf per thread).
// ---------------------------------------------------------------------------
__global__ __launch_bounds__(256) void k1_state(
    const float* __restrict__ nf,   // [768,64]
    const float* __restrict__ W1,   // [64,100]
    const float* __restrict__ b1,   // [64]
    const float* __restrict__ W2,   // [11,64]
    const float* __restrict__ b2,   // [11]
    const float* __restrict__ rot,  // [3,11,3]
    const float* __restrict__ ent,  // [3,10]
    const float* __restrict__ pw)   // [11]
{
    __shared__ float amps[SDIM];
    __shared__ float hbuf[64];
    __shared__ float f[NQ];
    __shared__ float scc[NG * 3], scs[NG * 3];
    __shared__ float Mg[NG][4];
    __shared__ float pent[NE];
    const int n   = blockIdx.x;
    const int tid = threadIdx.x;

    // --- feature preprocessor: h = relu(x @ W1[:, :64]^T + b1) ---
    const float* x = nf + n * FDIM;
    if (tid < 64) {
        float acc = b1[tid];
        const float* w = W1 + tid * 100;
        #pragma unroll 8
        for (int k = 0; k < 64; k++) acc = fmaf(x[k], w[k], acc);
        hbuf[tid] = fmaxf(acc, 0.f);
    }
    // init statevector |0...0>
    for (int s = tid; s < SDIM; s += 256) amps[s] = 0.f;
    if (tid == 0) amps[0] = 1.f;
    __syncthreads();

    if (tid < NQ) {
        float acc = b2[tid];
        const float* w = W2 + tid * 64;
        #pragma unroll 8
        for (int k = 0; k < 64; k++) acc = fmaf(hbuf[k], w[k], acc);
        f[tid] = tanhf(acc);
    }
    __syncthreads();

    // --- precompute (cos,sin) for all 99 (gate,axis) pairs: one per thread ---
    if (tid < NG * 3) {
        const int g  = tid / 3;          // gate index l*NQ+q
        const int q  = g % NQ;
        float ang = 0.5f * rot[tid] * f[q];  // rot flat [NL*NQ*3]
        float s_, c_;
        __sincosf(ang, &s_, &c_);
        scc[tid] = c_; scs[tid] = s_;
    }
    __syncthreads();

    // --- gate matrices + CNOT mixing coefficients ---
    if (tid < NG) {
        const float cx = scc[3*tid+0], sx = scs[3*tid+0];
        const float cy = scc[3*tid+1], sy = scs[3*tid+1];
        const float cz = scc[3*tid+2], sz = scs[3*tid+2];
        Mg[tid][0] =  cx * cy * cz;
        Mg[tid][1] = -sx * sy * sz;
        Mg[tid][2] =  sx * sy * cz;
        Mg[tid][3] =  cx * cy * sz;
    } else if (tid >= 64 && tid < 64 + NE) {
        const int e = tid - 64;
        pent[e] = 1.f / (1.f + __expf(-ent[e]));
    }
    __syncthreads();

    for (int l = 0; l < NL; l++) {
        // --- single-qubit rotations ---
        for (int q = 0; q < NQ; q++) {
            const int g = l * NQ + q;
            const float M00 = Mg[g][0], M01 = Mg[g][1];
            const float M10 = Mg[g][2], M11 = Mg[g][3];
            const int maskq = (1 << q) - 1;
            #pragma unroll
            for (int k = 0; k < 4; k++) {
                const int p  = tid + k * 256;              // 1024 pairs
                const int lo = ((p >> q) << (q + 1)) | (p & maskq);
                const int hi = lo | (1 << q);
                const float a = amps[lo], b = amps[hi];
                amps[lo] = fmaf(M00, a, M01 * b);
                amps[hi] = fmaf(M10, a, M11 * b);
            }
            __syncthreads();
        }
        // --- parameterized CNOTs ---
        for (int q = 0; q < NQ - 1; q++) {
            const float pm = pent[l * (NQ - 1) + q];
            const int maskq = (1 << q) - 1;
            #pragma unroll
            for (int k = 0; k < 2; k++) {
                const int j  = tid + k * 256;              // 512 pairs
                const int s0 = ((j >> q) << (q + 2)) | (1 << q) | (j & maskq);
                const int s1 = s0 | (2 << q);
                const float a = amps[s0], b = amps[s1];
                amps[s0] = fmaf(pm, b - a, a);
                amps[s1] = fmaf(pm, a - b, b);
            }
            __syncthreads();
        }
    }

    // --- write pool-weighted amps ---
    const float wa = 1.f / (1.f + __expf(-pw[(n % AA) % NQ]));
    float* dst = g_scratch + (size_t)n * SDIM;
    for (int s = tid; s < SDIM; s += 256) dst[s] = amps[s] * wa;
}

// ---------------------------------------------------------------------------
// Kernel 2: grid = BB*K2CH CTAs. CTA (b,ch) handles 256 s-values: R = sum_a,
// accumulate partial {R^2, R cos phi, R sin phi} -> g_part. No atomics.
// ---------------------------------------------------------------------------
__global__ __launch_bounds__(256) void k2_pool(const float* __restrict__ msg) // [3,11,3]
{
    __shared__ float theta[NQ];
    __shared__ float red[3][256];
    const int blk = blockIdx.x;
    const int b   = blk / K2CH;
    const int ch  = blk % K2CH;
    const int tid = threadIdx.x;

    if (tid < NQ) {
        float t = 0.f;
        for (int l = 0; l < NL; l++)
            for (int c = 0; c < 3; c++)
                t += msg[(l * NQ + tid) * 3 + c];
        theta[tid] = t;
    }
    __syncthreads();

    const int s = ch * 256 + tid;
    const float* base = g_scratch + (size_t)(b * AA) * SDIM + s;
    float r0 = 0.f, r1 = 0.f, r2 = 0.f, r3 = 0.f;
    #pragma unroll
    for (int a = 0; a < AA; a += 4) {
        r0 += base[(size_t)(a + 0) * SDIM];
        r1 += base[(size_t)(a + 1) * SDIM];
        r2 += base[(size_t)(a + 2) * SDIM];
        r3 += base[(size_t)(a + 3) * SDIM];
    }
    const float R = (r0 + r1) + (r2 + r3);

    float phi = 0.f;
    #pragma unroll
    for (int q = 0; q < NQ; q++) if ((s >> q) & 1) phi += theta[q];
    float cp, sp;
    sincosf(phi, &sp, &cp);   // accurate: phi can be O(10)

    red[0][tid] = R * R;
    red[1][tid] = R * cp;
    red[2][tid] = R * sp;
    __syncthreads();
    for (int st = 128; st > 0; st >>= 1) {
        if (tid < st) {
            red[0][tid] += red[0][tid + st];
            red[1][tid] += red[1][tid + st];
            red[2][tid] += red[2][tid + st];
        }
        __syncthreads();
    }
    if (tid == 0) {
        g_part[blk * 3 + 0] = red[0][0];
        g_part[blk * 3 + 1] = red[1][0];
        g_part[blk * 3 + 2] = red[2][0];
    }
}

// ---------------------------------------------------------------------------
// Kernel 3: single CTA. Final stat reduce -> rep, then MLP with all weights
// staged through shared memory (coalesced loads, bank-padded rows) and
// k-outer loops keeping 8 batch accumulators.
// ---------------------------------------------------------------------------
__global__ __launch_bounds__(256) void k3_mlp(
    const float* __restrict__ Wo1, const float* __restrict__ bo1,   // [256,22],[256]
    const float* __restrict__ Wo2, const float* __restrict__ bo2,   // [128,256],[128]
    const float* __restrict__ Wo3, const float* __restrict__ bo3,   // [64,128],[64]
    float* __restrict__ out)                                        // [8,64]
{
    __shared__ float wtile[128 * 65];   // 33.3 KB: Wo2 chunk / Wo1 flat / Wo3 padded
    __shared__ float h1s[BB][256];
    __shared__ float h2s[BB][128];
    __shared__ float rep[BB][22];
    const int tid = threadIdx.x;

    // --- final reduce of partial stats -> rep ---
    if (tid < BB) {
        float s2 = 0.f, sc = 0.f, ss = 0.f;
        for (int ch = 0; ch < K2CH; ch++) {
            const int o = (tid * K2CH + ch) * 3;
            s2 += g_part[o + 0];
            sc += g_part[o + 1];
            ss += g_part[o + 2];
        }
        const float inv = 1.f / (fmaxf(sqrtf(s2), 1e-12f) * (float)SDIM);
        const float rm = sc * inv, im = ss * inv;
        for (int q = 0; q < NQ; q++) { rep[tid][q] = rm; rep[tid][NQ + q] = im; }
    }

    // --- layer 1: stage Wo1 (coalesced), compute with 8 batch accumulators ---
    for (int i = tid; i < 256 * 22; i += 256) wtile[i] = Wo1[i];
    __syncthreads();
    {
        float acc[BB];
        const float bias = bo1[tid];
        #pragma unroll
        for (int b = 0; b < BB; b++) acc[b] = bias;
        #pragma unroll
        for (int k = 0; k < 22; k++) {
            const float w = wtile[tid * 22 + k];
            #pragma unroll
            for (int b = 0; b < BB; b++) acc[b] = fmaf(w, rep[b][k], acc[b]);
        }
        #pragma unroll
        for (int b = 0; b < BB; b++) h1s[b][tid] = fmaxf(acc[b], 0.f);
    }

    // --- layer 2: 4 chunks of 64 k-values, Wo2 staged with pad-65 rows ---
    float acc2[BB];
    if (tid < 128) {
        const float bias = bo2[tid];
        #pragma unroll
        for (int b = 0; b < BB; b++) acc2[b] = bias;
    }
    for (int c = 0; c < 4; c++) {
        __syncthreads();   // wtile reuse barrier (also orders h1s writes at c=0)
        for (int i = tid; i < 128 * 64; i += 256) {
            const int o = i >> 6, kk = i & 63;
            wtile[o * 65 + kk] = Wo2[o * 256 + c * 64 + kk];
        }
        __syncthreads();
        if (tid < 128) {
            #pragma unroll 8
            for (int kk = 0; kk < 64; kk++) {
                const float w = wtile[tid * 65 + kk];
                const int kg = c * 64 + kk;
                #pragma unroll
                for (int b = 0; b < BB; b++) acc2[b] = fmaf(w, h1s[b][kg], acc2[b]);
            }
        }
    }
    if (tid < 128) {
        #pragma unroll
        for (int b = 0; b < BB; b++) h2s[b][tid] = fmaxf(acc2[b], 0.f);
    }
    __syncthreads();

    // --- layer 3: Wo3 staged with pad-129 rows ---
    for (int i = tid; i < 64 * 128; i += 256) {
        const int o = i >> 7, k = i & 127;
        wtile[o * 129 + k] = Wo3[i];
    }
    __syncthreads();
    if (tid < 64) {
        float acc3[BB];
        const float bias = bo3[tid];
        #pragma unroll
        for (int b = 0; b < BB; b++) acc3[b] = bias;
        #pragma unroll 8
        for (int k = 0; k < 128; k++) {
            const float w = wtile[tid * 129 + k];
            #pragma unroll
            for (int b = 0; b < BB; b++) acc3[b] = fmaf(w, h2s[b][k], acc3[b]);
        }
        #pragma unroll
        for (int b = 0; b < BB; b++) out[b * 64 + tid] = acc3[b];
    }
}

// ---------------------------------------------------------------------------
extern "C" void kernel_launch(void* const* d_in, const int* in_sizes, int n_in,
                              void* d_out, int out_size)
{
    const float* nf   = (const float*)d_in[0];
    // d_in[1] = edge_indices (int32) — unused by the math
    const float* W1   = (const float*)d_in[2];
    const float* b1   = (const float*)d_in[3];
    const float* W2   = (const float*)d_in[4];
    const float* b2   = (const float*)d_in[5];
    const float* rot  = (const float*)d_in[6];
    const float* ent  = (const float*)d_in[7];
    const float* msg  = (const float*)d_in[8];
    const float* pw   = (const float*)d_in[9];
    const float* Wo1  = (const float*)d_in[10];
    const float* bo1  = (const float*)d_in[11];
    const float* Wo2  = (const float*)d_in[12];
    const float* bo2  = (const float*)d_in[13];
    const float* Wo3  = (const float*)d_in[14];
    const float* bo3  = (const float*)d_in[15];
    float* out = (float*)d_out;

    k1_state<<<NSTATE, 256>>>(nf, W1, b1, W2, b2, rot, ent, pw);
    k2_pool<<<BB * K2CH, 256>>>(msg);
    k3_mlp<<<1, 256>>>(Wo1, bo1, Wo2, bo2, Wo3, bo3, out);
}

// round 8
// speedup vs baseline: 6.1002x; 1.3663x over previous
#include <cuda_runtime.h>
#include <math.h>

#define NQ 11
#define NL 3
#define SDIM 2048          // 2^NQ
#define BB 8
#define AA 96
#define NSTATE (BB*AA)     // 768
#define FDIM 64
#define NG (NL*NQ)         // 33 rotation gates
#define NE (NL*(NQ-1))     // 30 CNOT gates
#define K2CH 8             // s-chunks per batch in k2

// Scratch (no cudaMalloc allowed)
__device__ float g_scratch[NSTATE * SDIM];       // 6 MB pool-weighted amps
__device__ float g_part[BB * K2CH * 3];          // partial {sumR2,sumRcos,sumRsin}

// ---------------------------------------------------------------------------
// Kernel 1: one CTA per state n. Register-resident statevector:
//   thread tid holds r[k] = amps[(k<<8) | tid],  k = 0..7
//   state bits: [4:0]=lane, [7:5]=warp, [10:8]=register index
// Gates on lane bits -> shfl_xor; register bits -> pure FMA;
// warp bits -> double-buffered smem exchange (ONE barrier per gate).
// ---------------------------------------------------------------------------
__global__ __launch_bounds__(256) void k1_state(
    const float* __restrict__ nf,   // [768,64]
    const float* __restrict__ W1,   // [64,100]
    const float* __restrict__ b1,   // [64]
    const float* __restrict__ W2,   // [11,64]
    const float* __restrict__ b2,   // [11]
    const float* __restrict__ rot,  // [3,11,3] flat
    const float* __restrict__ ent,  // [3,10]
    const float* __restrict__ pw)   // [11]
{
    __shared__ float xbuf[2][SDIM];          // 16KB double-buffered exchange
    __shared__ float hbuf[64];
    __shared__ float f[NQ];
    __shared__ float scc[NG * 3], scs[NG * 3];
    __shared__ float Mg[NG][4];
    __shared__ float pent[NE];
    const int n    = blockIdx.x;
    const int tid  = threadIdx.x;
    const int lane = tid & 31;

    // --- feature preprocessor: h = relu(x @ W1[:, :64]^T + b1) ---
    const float* x = nf + n * FDIM;
    if (tid < 64) {
        float acc = b1[tid];
        const float* w = W1 + tid * 100;
        #pragma unroll 8
        for (int k = 0; k < 64; k++) acc = fmaf(x[k], w[k], acc);
        hbuf[tid] = fmaxf(acc, 0.f);
    }
    __syncthreads();

    if (tid < NQ) {
        float acc = b2[tid];
        const float* w = W2 + tid * 64;
        #pragma unroll 8
        for (int k = 0; k < 64; k++) acc = fmaf(hbuf[k], w[k], acc);
        f[tid] = tanhf(acc);
    }
    __syncthreads();

    // --- (cos,sin) for all 99 (gate,axis) pairs: one per thread ---
    if (tid < NG * 3) {
        const int g = tid / 3;
        const int q = g % NQ;
        float s_, c_;
        __sincosf(0.5f * rot[tid] * f[q], &s_, &c_);
        scc[tid] = c_; scs[tid] = s_;
    }
    __syncthreads();

    // --- gate matrices + CNOT mixing coefficients ---
    if (tid < NG) {
        const float cx = scc[3*tid+0], sx = scs[3*tid+0];
        const float cy = scc[3*tid+1], sy = scs[3*tid+1];
        const float cz = scc[3*tid+2], sz = scs[3*tid+2];
        Mg[tid][0] =  cx * cy * cz;
        Mg[tid][1] = -sx * sy * sz;
        Mg[tid][2] =  sx * sy * cz;
        Mg[tid][3] =  cx * cy * sz;
    } else if (tid >= 64 && tid < 64 + NE) {
        const int e = tid - 64;
        pent[e] = 1.f / (1.f + __expf(-ent[e]));
    }

    // --- register-resident statevector, init |0...0> ---
    float r[8];
    #pragma unroll
    for (int k = 0; k < 8; k++) r[k] = 0.f;
    if (tid == 0) r[0] = 1.f;
    __syncthreads();

    int phase = 0;
    for (int l = 0; l < NL; l++) {
        // ================= single-qubit rotations =================
        // qubits 0..4 : lane bits -> shfl_xor, no barrier
        #pragma unroll
        for (int q = 0; q < 5; q++) {
            const int g = l * NQ + q;
            const float M00 = Mg[g][0], M01 = Mg[g][1];
            const float M10 = Mg[g][2], M11 = Mg[g][3];
            const int m = 1 << q;
            const bool h = (lane & m) != 0;
            const float co = h ? M11 : M00;   // coef on own value
            const float ct = h ? M10 : M01;   // coef on partner value
            #pragma unroll
            for (int k = 0; k < 8; k++) {
                const float o = __shfl_xor_sync(0xffffffffu, r[k], m);
                r[k] = fmaf(co, r[k], ct * o);
            }
        }
        // qubits 5..7 : warp bits -> smem exchange (1 barrier each)
        #pragma unroll
        for (int q = 5; q < 8; q++) {
            const int g = l * NQ + q;
            const float M00 = Mg[g][0], M01 = Mg[g][1];
            const float M10 = Mg[g][2], M11 = Mg[g][3];
            const int m = 1 << q;
            float* buf = xbuf[phase]; phase ^= 1;
            #pragma unroll
            for (int k = 0; k < 8; k++) buf[k * 256 + tid] = r[k];
            __syncthreads();
            const int pt = tid ^ m;
            const bool h = (tid & m) != 0;
            const float co = h ? M11 : M00;
            const float ct = h ? M10 : M01;
            #pragma unroll
            for (int k = 0; k < 8; k++)
                r[k] = fmaf(co, r[k], ct * buf[k * 256 + pt]);
        }
        // qubits 8..10 : register bits -> pure FMA
        #pragma unroll
        for (int j = 0; j < 3; j++) {
            const int g = l * NQ + 8 + j;
            const float M00 = Mg[g][0], M01 = Mg[g][1];
            const float M10 = Mg[g][2], M11 = Mg[g][3];
            #pragma unroll
            for (int k = 0; k < 8; k++) {
                if (!((k >> j) & 1)) {
                    const int k2 = k | (1 << j);
                    const float a = r[k], b = r[k2];
                    r[k]  = fmaf(M00, a, M01 * b);
                    r[k2] = fmaf(M10, a, M11 * b);
                }
            }
        }
        // ================= parameterized CNOTs (ctrl bit q, comm bit q+1) ===
        // q = 0..3 : comm = lane bit -> shfl
        #pragma unroll
        for (int q = 0; q < 4; q++) {
            const float p = pent[l * (NQ - 1) + q];
            const int m2 = 2 << q;
            const bool c = (lane & (1 << q)) != 0;
            #pragma unroll
            for (int k = 0; k < 8; k++) {
                const float o = __shfl_xor_sync(0xffffffffu, r[k], m2);
                const float mixed = fmaf(p, o - r[k], r[k]);
                r[k] = c ? mixed : r[k];
            }
        }
        // q = 4..6 : comm = warp bit -> smem exchange
        #pragma unroll
        for (int q = 4; q < 7; q++) {
            const float p = pent[l * (NQ - 1) + q];
            const int m2 = 2 << q;               // 32, 64, 128
            float* buf = xbuf[phase]; phase ^= 1;
            #pragma unroll
            for (int k = 0; k < 8; k++) buf[k * 256 + tid] = r[k];
            __syncthreads();
            const int pt = tid ^ m2;
            const bool c = (tid & (1 << q)) != 0;
            #pragma unroll
            for (int k = 0; k < 8; k++) {
                const float o = buf[k * 256 + pt];
                const float mixed = fmaf(p, o - r[k], r[k]);
                r[k] = c ? mixed : r[k];
            }
        }
        // q = 7 : ctrl = tid bit 7, comm = register bit 0 -> pairs (k, k+1)
        {
            const float p = pent[l * (NQ - 1) + 7];
            if (tid & 128) {
                #pragma unroll
                for (int k = 0; k < 8; k += 2) {
                    const float a = r[k], b = r[k + 1];
                    r[k]     = fmaf(p, b - a, a);
                    r[k + 1] = fmaf(p, a - b, b);
                }
            }
        }
        // q = 8 : ctrl = reg bit 0, comm = reg bit 1 -> pairs (1,3),(5,7)
        {
            const float p = pent[l * (NQ - 1) + 8];
            { const float a = r[1], b = r[3]; r[1] = fmaf(p, b - a, a); r[3] = fmaf(p, a - b, b); }
            { const float a = r[5], b = r[7]; r[5] = fmaf(p, b - a, a); r[7] = fmaf(p, a - b, b); }
        }
        // q = 9 : ctrl = reg bit 1, comm = reg bit 2 -> pairs (2,6),(3,7)
        {
            const float p = pent[l * (NQ - 1) + 9];
            { const float a = r[2], b = r[6]; r[2] = fmaf(p, b - a, a); r[6] = fmaf(p, a - b, b); }
            { const float a = r[3], b = r[7]; r[3] = fmaf(p, b - a, a); r[7] = fmaf(p, a - b, b); }
        }
    }

    // --- write pool-weighted amps (coalesced) ---
    const float wa = 1.f / (1.f + __expf(-pw[(n % AA) % NQ]));
    float* dst = g_scratch + (size_t)n * SDIM;
    #pragma unroll
    for (int k = 0; k < 8; k++) dst[k * 256 + tid] = r[k] * wa;
}

// ---------------------------------------------------------------------------
// Kernel 2: grid = BB*K2CH CTAs. CTA (b,ch) handles 256 s-values: R = sum_a,
// accumulate partial {R^2, R cos phi, R sin phi} -> g_part. 8 accumulators
// to keep 96 independent L2 loads in flight.
// ---------------------------------------------------------------------------
__global__ __launch_bounds__(256) void k2_pool(const float* __restrict__ msg) // [3,11,3]
{
    __shared__ float theta[NQ];
    __shared__ float red[3][256];
    const int blk = blockIdx.x;
    const int b   = blk / K2CH;
    const int ch  = blk % K2CH;
    const int tid = threadIdx.x;

    if (tid < NQ) {
        float t = 0.f;
        for (int l = 0; l < NL; l++)
            for (int c = 0; c < 3; c++)
                t += msg[(l * NQ + tid) * 3 + c];
        theta[tid] = t;
    }
    __syncthreads();

    const int s = ch * 256 + tid;
    const float* base = g_scratch + (size_t)(b * AA) * SDIM + s;
    float acc[8];
    #pragma unroll
    for (int j = 0; j < 8; j++) acc[j] = 0.f;
    #pragma unroll
    for (int a = 0; a < AA; a += 8) {
        #pragma unroll
        for (int j = 0; j < 8; j++)
            acc[j] += base[(size_t)(a + j) * SDIM];
    }
    const float R = ((acc[0] + acc[1]) + (acc[2] + acc[3]))
                  + ((acc[4] + acc[5]) + (acc[6] + acc[7]));

    float phi = 0.f;
    #pragma unroll
    for (int q = 0; q < NQ; q++) if ((s >> q) & 1) phi += theta[q];
    float cp, sp;
    sincosf(phi, &sp, &cp);   // accurate: phi can be O(10)

    red[0][tid] = R * R;
    red[1][tid] = R * cp;
    red[2][tid] = R * sp;
    __syncthreads();
    for (int st = 128; st > 0; st >>= 1) {
        if (tid < st) {
            red[0][tid] += red[0][tid + st];
            red[1][tid] += red[1][tid + st];
            red[2][tid] += red[2][tid + st];
        }
        __syncthreads();
    }
    if (tid == 0) {
        g_part[blk * 3 + 0] = red[0][0];
        g_part[blk * 3 + 1] = red[1][0];
        g_part[blk * 3 + 2] = red[2][0];
    }
}

// ---------------------------------------------------------------------------
// Kernel 3: single CTA. Final stat reduce -> rep, then MLP with all weights
// staged through shared memory (coalesced loads, bank-padded rows) and
// k-outer loops keeping 8 batch accumulators.
// ---------------------------------------------------------------------------
__global__ __launch_bounds__(256) void k3_mlp(
    const float* __restrict__ Wo1, const float* __restrict__ bo1,   // [256,22],[256]
    const float* __restrict__ Wo2, const float* __restrict__ bo2,   // [128,256],[128]
    const float* __restrict__ Wo3, const float* __restrict__ bo3,   // [64,128],[64]
    float* __restrict__ out)                                        // [8,64]
{
    __shared__ float wtile[128 * 65];   // Wo2 chunk / Wo1 flat / Wo3 padded
    __shared__ float h1s[BB][256];
    __shared__ float h2s[BB][128];
    __shared__ float rep[BB][22];
    const int tid = threadIdx.x;

    // --- final reduce of partial stats -> rep ---
    if (tid < BB) {
        float s2 = 0.f, sc = 0.f, ss = 0.f;
        for (int ch = 0; ch < K2CH; ch++) {
            const int o = (tid * K2CH + ch) * 3;
            s2 += g_part[o + 0];
            sc += g_part[o + 1];
            ss += g_part[o + 2];
        }
        const float inv = 1.f / (fmaxf(sqrtf(s2), 1e-12f) * (float)SDIM);
        const float rm = sc * inv, im = ss * inv;
        for (int q = 0; q < NQ; q++) { rep[tid][q] = rm; rep[tid][NQ + q] = im; }
    }

    // --- layer 1: stage Wo1 (coalesced), 8 batch accumulators ---
    for (int i = tid; i < 256 * 22; i += 256) wtile[i] = Wo1[i];
    __syncthreads();
    {
        float acc[BB];
        const float bias = bo1[tid];
        #pragma unroll
        for (int b = 0; b < BB; b++) acc[b] = bias;
        #pragma unroll
        for (int k = 0; k < 22; k++) {
            const float w = wtile[tid * 22 + k];
            #pragma unroll
            for (int b = 0; b < BB; b++) acc[b] = fmaf(w, rep[b][k], acc[b]);
        }
        #pragma unroll
        for (int b = 0; b < BB; b++) h1s[b][tid] = fmaxf(acc[b], 0.f);
    }

    // --- layer 2: 4 chunks of 64 k-values, Wo2 staged with pad-65 rows ---
    float acc2[BB];
    if (tid < 128) {
        const float bias = bo2[tid];
        #pragma unroll
        for (int b = 0; b < BB; b++) acc2[b] = bias;
    }
    for (int c = 0; c < 4; c++) {
        __syncthreads();   // wtile reuse barrier (also orders h1s writes at c=0)
        for (int i = tid; i < 128 * 64; i += 256) {
            const int o = i >> 6, kk = i & 63;
            wtile[o * 65 + kk] = Wo2[o * 256 + c * 64 + kk];
        }
        __syncthreads();
        if (tid < 128) {
            #pragma unroll 8
            for (int kk = 0; kk < 64; kk++) {
                const float w = wtile[tid * 65 + kk];
                const int kg = c * 64 + kk;
                #pragma unroll
                for (int b = 0; b < BB; b++) acc2[b] = fmaf(w, h1s[b][kg], acc2[b]);
            }
        }
    }
    if (tid < 128) {
        #pragma unroll
        for (int b = 0; b < BB; b++) h2s[b][tid] = fmaxf(acc2[b], 0.f);
    }
    __syncthreads();

    // --- layer 3: Wo3 staged with pad-129 rows ---
    for (int i = tid; i < 64 * 128; i += 256) {
        const int o = i >> 7, k = i & 127;
        wtile[o * 129 + k] = Wo3[i];
    }
    __syncthreads();
    if (tid < 64) {
        float acc3[BB];
        const float bias = bo3[tid];
        #pragma unroll
        for (int b = 0; b < BB; b++) acc3[b] = bias;
        #pragma unroll 8
        for (int k = 0; k < 128; k++) {
            const float w = wtile[tid * 129 + k];
            #pragma unroll
            for (int b = 0; b < BB; b++) acc3[b] = fmaf(w, h2s[b][k], acc3[b]);
        }
        #pragma unroll
        for (int b = 0; b < BB; b++) out[b * 64 + tid] = acc3[b];
    }
}

// ---------------------------------------------------------------------------
extern "C" void kernel_launch(void* const* d_in, const int* in_sizes, int n_in,
                              void* d_out, int out_size)
{
    const float* nf   = (const float*)d_in[0];
    // d_in[1] = edge_indices (int32) — unused by the math
    const float* W1   = (const float*)d_in[2];
    const float* b1   = (const float*)d_in[3];
    const float* W2   = (const float*)d_in[4];
    const float* b2   = (const float*)d_in[5];
    const float* rot  = (const float*)d_in[6];
    const float* ent  = (const float*)d_in[7];
    const float* msg  = (const float*)d_in[8];
    const float* pw   = (const float*)d_in[9];
    const float* Wo1  = (const float*)d_in[10];
    const float* bo1  = (const float*)d_in[11];
    const float* Wo2  = (const float*)d_in[12];
    const float* bo2  = (const float*)d_in[13];
    const float* Wo3  = (const float*)d_in[14];
    const float* bo3  = (const float*)d_in[15];
    float* out = (float*)d_out;

    k1_state<<<NSTATE, 256>>>(nf, W1, b1, W2, b2, rot, ent, pw);
    k2_pool<<<BB * K2CH, 256>>>(msg);
    k3_mlp<<<1, 256>>>(Wo1, bo1, Wo2, bo2, Wo3, bo3, out);
}

// round 9
// speedup vs baseline: 6.6250x; 1.0860x over previous
#include <cuda_runtime.h>
#include <math.h>

#define NQ 11
#define NL 3
#define SDIM 2048          // 2^NQ
#define BB 8
#define AA 96
#define NSTATE (BB*AA)     // 768
#define FDIM 64
#define NG (NL*NQ)         // 33 rotation gates
#define NE (NL*(NQ-1))     // 30 CNOT gates
#define K2CH 8             // s-chunks per batch in k2

// Scratch (no cudaMalloc allowed)
__device__ float g_scratch[NSTATE * SDIM];       // 6 MB pool-weighted amps
__device__ float g_part[BB * K2CH * 3];          // partial {sumR2,sumRcos,sumRsin}

// ---------------------------------------------------------------------------
// Kernel 1: one CTA per state n. Register-resident statevector:
//   thread tid holds r[k] = amps[(k<<8) | tid],  k = 0..7
//   state bits: [4:0]=lane, [7:5]=warp, [10:8]=register index
// Rotations commute -> reorder freely. Per layer only TWO smem transposes
// (swap bits [10:8] <-> [7:5]) so every non-lane gate is a register FMA.
// CNOT chain order q=0..9 is preserved exactly.
// ---------------------------------------------------------------------------
__global__ __launch_bounds__(256) void k1_state(
    const float* __restrict__ nf,   // [768,64]
    const float* __restrict__ W1,   // [64,100]
    const float* __restrict__ b1,   // [64]
    const float* __restrict__ W2,   // [11,64]
    const float* __restrict__ b2,   // [11]
    const float* __restrict__ rot,  // [3,11,3] flat
    const float* __restrict__ ent,  // [3,10]
    const float* __restrict__ pw)   // [11]
{
    __shared__ float xbuf[2][SDIM];          // 16KB double-buffered transpose
    __shared__ float hbuf[64];
    __shared__ float f[NQ];
    __shared__ float scc[NG * 3], scs[NG * 3];
    __shared__ float Mg[NG][4];
    __shared__ float pent[NE];
    const int n    = blockIdx.x;
    const int tid  = threadIdx.x;
    const int lane = tid & 31;

    // --- feature preprocessor: h = relu(x @ W1[:, :64]^T + b1) ---
    const float* x = nf + n * FDIM;
    if (tid < 64) {
        float acc = b1[tid];
        const float* w = W1 + tid * 100;
        #pragma unroll 8
        for (int k = 0; k < 64; k++) acc = fmaf(x[k], w[k], acc);
        hbuf[tid] = fmaxf(acc, 0.f);
    }
    __syncthreads();

    if (tid < NQ) {
        float acc = b2[tid];
        const float* w = W2 + tid * 64;
        #pragma unroll 8
        for (int k = 0; k < 64; k++) acc = fmaf(hbuf[k], w[k], acc);
        f[tid] = tanhf(acc);
    }
    __syncthreads();

    // --- (cos,sin) for all 99 (gate,axis) pairs: one per thread ---
    if (tid < NG * 3) {
        const int g = tid / 3;
        const int q = g % NQ;
        float s_, c_;
        __sincosf(0.5f * rot[tid] * f[q], &s_, &c_);
        scc[tid] = c_; scs[tid] = s_;
    }
    __syncthreads();

    // --- gate matrices + CNOT mixing coefficients ---
    if (tid < NG) {
        const float cx = scc[3*tid+0], sx = scs[3*tid+0];
        const float cy = scc[3*tid+1], sy = scs[3*tid+1];
        const float cz = scc[3*tid+2], sz = scs[3*tid+2];
        Mg[tid][0] =  cx * cy * cz;
        Mg[tid][1] = -sx * sy * sz;
        Mg[tid][2] =  sx * sy * cz;
        Mg[tid][3] =  cx * cy * sz;
    } else if (tid >= 64 && tid < 64 + NE) {
        const int e = tid - 64;
        pent[e] = 1.f / (1.f + __expf(-ent[e]));
    }

    // --- register-resident statevector, init |0...0> ---
    float r[8];
    #pragma unroll
    for (int k = 0; k < 8; k++) r[k] = 0.f;
    if (tid == 0) r[0] = 1.f;
    __syncthreads();

    const int wbits = (tid >> 5) & 7;             // state bits [7:5]
    const int tbase = (wbits << 8) | lane;        // transpose read base

    for (int l = 0; l < NL; l++) {
        // ---- rotations on lane qubits 0..4 : shfl_xor ----
        #pragma unroll
        for (int q = 0; q < 5; q++) {
            const int g = l * NQ + q;
            const float M00 = Mg[g][0], M01 = Mg[g][1];
            const float M10 = Mg[g][2], M11 = Mg[g][3];
            const int m = 1 << q;
            const bool h = (lane & m) != 0;
            const float co = h ? M11 : M00;
            const float ct = h ? M10 : M01;
            #pragma unroll
            for (int k = 0; k < 8; k++) {
                const float o = __shfl_xor_sync(0xffffffffu, r[k], m);
                r[k] = fmaf(co, r[k], ct * o);
            }
        }
        // ---- rotations on register qubits 8,9,10 : pure FMA ----
        #pragma unroll
        for (int j = 0; j < 3; j++) {
            const int g = l * NQ + 8 + j;
            const float M00 = Mg[g][0], M01 = Mg[g][1];
            const float M10 = Mg[g][2], M11 = Mg[g][3];
            #pragma unroll
            for (int k = 0; k < 8; k++) {
                if (!((k >> j) & 1)) {
                    const int k2 = k | (1 << j);
                    const float a = r[k], b = r[k2];
                    r[k]  = fmaf(M00, a, M01 * b);
                    r[k2] = fmaf(M10, a, M11 * b);
                }
            }
        }
        // ---- TRANSPOSE: swap state bits [10:8] <-> [7:5] ----
        // after: reg bit j = qubit 5+j, warp bits = qubits 8,9,10
        {
            float* buf = xbuf[0];
            #pragma unroll
            for (int k = 0; k < 8; k++) buf[k * 256 + tid] = r[k];
            __syncthreads();
            #pragma unroll
            for (int k = 0; k < 8; k++) r[k] = buf[tbase + (k << 5)];
        }
        // ---- rotations on qubits 5,6,7 (now register bits) : FMA ----
        #pragma unroll
        for (int j = 0; j < 3; j++) {
            const int g = l * NQ + 5 + j;
            const float M00 = Mg[g][0], M01 = Mg[g][1];
            const float M10 = Mg[g][2], M11 = Mg[g][3];
            #pragma unroll
            for (int k = 0; k < 8; k++) {
                if (!((k >> j) & 1)) {
                    const int k2 = k | (1 << j);
                    const float a = r[k], b = r[k2];
                    r[k]  = fmaf(M00, a, M01 * b);
                    r[k2] = fmaf(M10, a, M11 * b);
                }
            }
        }
        // ---- CNOT chain, in order q = 0..9 ----
        // q = 0..3 : ctrl lane bit q, comm lane bit q+1 -> shfl
        #pragma unroll
        for (int q = 0; q < 4; q++) {
            const float p = pent[l * (NQ - 1) + q];
            const int m2 = 2 << q;
            const bool c = (lane & (1 << q)) != 0;
            #pragma unroll
            for (int k = 0; k < 8; k++) {
                const float o = __shfl_xor_sync(0xffffffffu, r[k], m2);
                const float mixed = fmaf(p, o - r[k], r[k]);
                r[k] = c ? mixed : r[k];
            }
        }
        // q = 4 : ctrl lane bit 4, comm qubit5 = reg bit 0
        {
            const float p = pent[l * (NQ - 1) + 4];
            if (lane & 16) {
                #pragma unroll
                for (int k = 0; k < 8; k += 2) {
                    const float a = r[k], b = r[k + 1];
                    r[k]     = fmaf(p, b - a, a);
                    r[k + 1] = fmaf(p, a - b, b);
                }
            }
        }
        // q = 5 : ctrl reg bit 0, comm reg bit 1 -> (1,3),(5,7)
        {
            const float p = pent[l * (NQ - 1) + 5];
            { const float a = r[1], b = r[3]; r[1] = fmaf(p, b - a, a); r[3] = fmaf(p, a - b, b); }
            { const float a = r[5], b = r[7]; r[5] = fmaf(p, b - a, a); r[7] = fmaf(p, a - b, b); }
        }
        // q = 6 : ctrl reg bit 1, comm reg bit 2 -> (2,6),(3,7)
        {
            const float p = pent[l * (NQ - 1) + 6];
            { const float a = r[2], b = r[6]; r[2] = fmaf(p, b - a, a); r[6] = fmaf(p, a - b, b); }
            { const float a = r[3], b = r[7]; r[3] = fmaf(p, b - a, a); r[7] = fmaf(p, a - b, b); }
        }
        // ---- TRANSPOSE BACK (involution) ----
        {
            float* buf = xbuf[1];
            #pragma unroll
            for (int k = 0; k < 8; k++) buf[k * 256 + tid] = r[k];
            __syncthreads();
            #pragma unroll
            for (int k = 0; k < 8; k++) r[k] = buf[tbase + (k << 5)];
        }
        // q = 7 : ctrl tid bit 7, comm bit 8 = reg bit 0
        {
            const float p = pent[l * (NQ - 1) + 7];
            if (tid & 128) {
                #pragma unroll
                for (int k = 0; k < 8; k += 2) {
                    const float a = r[k], b = r[k + 1];
                    r[k]     = fmaf(p, b - a, a);
                    r[k + 1] = fmaf(p, a - b, b);
                }
            }
        }
        // q = 8 : ctrl reg bit 0, comm reg bit 1 -> (1,3),(5,7)
        {
            const float p = pent[l * (NQ - 1) + 8];
            { const float a = r[1], b = r[3]; r[1] = fmaf(p, b - a, a); r[3] = fmaf(p, a - b, b); }
            { const float a = r[5], b = r[7]; r[5] = fmaf(p, b - a, a); r[7] = fmaf(p, a - b, b); }
        }
        // q = 9 : ctrl reg bit 1, comm reg bit 2 -> (2,6),(3,7)
        {
            const float p = pent[l * (NQ - 1) + 9];
            { const float a = r[2], b = r[6]; r[2] = fmaf(p, b - a, a); r[6] = fmaf(p, a - b, b); }
            { const float a = r[3], b = r[7]; r[3] = fmaf(p, b - a, a); r[7] = fmaf(p, a - b, b); }
        }
    }

    // --- write pool-weighted amps (coalesced) ---
    const float wa = 1.f / (1.f + __expf(-pw[(n % AA) % NQ]));
    float* dst = g_scratch + (size_t)n * SDIM;
    #pragma unroll
    for (int k = 0; k < 8; k++) dst[k * 256 + tid] = r[k] * wa;
}

// ---------------------------------------------------------------------------
// Kernel 2: grid = BB*K2CH CTAs. CTA (b,ch) handles 256 s-values: R = sum_a,
// accumulate partial {R^2, R cos phi, R sin phi} -> g_part. 8 accumulators
// to keep 96 independent L2 loads in flight.
// ---------------------------------------------------------------------------
__global__ __launch_bounds__(256) void k2_pool(const float* __restrict__ msg) // [3,11,3]
{
    __shared__ float theta[NQ];
    __shared__ float red[3][256];
    const int blk = blockIdx.x;
    const int b   = blk / K2CH;
    const int ch  = blk % K2CH;
    const int tid = threadIdx.x;

    if (tid < NQ) {
        float t = 0.f;
        for (int l = 0; l < NL; l++)
            for (int c = 0; c < 3; c++)
                t += msg[(l * NQ + tid) * 3 + c];
        theta[tid] = t;
    }
    __syncthreads();

    const int s = ch * 256 + tid;
    const float* base = g_scratch + (size_t)(b * AA) * SDIM + s;
    float acc[8];
    #pragma unroll
    for (int j = 0; j < 8; j++) acc[j] = 0.f;
    #pragma unroll
    for (int a = 0; a < AA; a += 8) {
        #pragma unroll
        for (int j = 0; j < 8; j++)
            acc[j] += base[(size_t)(a + j) * SDIM];
    }
    const float R = ((acc[0] + acc[1]) + (acc[2] + acc[3]))
                  + ((acc[4] + acc[5]) + (acc[6] + acc[7]));

    float phi = 0.f;
    #pragma unroll
    for (int q = 0; q < NQ; q++) if ((s >> q) & 1) phi += theta[q];
    float cp, sp;
    sincosf(phi, &sp, &cp);   // accurate: phi can be O(10)

    red[0][tid] = R * R;
    red[1][tid] = R * cp;
    red[2][tid] = R * sp;
    __syncthreads();
    for (int st = 128; st > 0; st >>= 1) {
        if (tid < st) {
            red[0][tid] += red[0][tid + st];
            red[1][tid] += red[1][tid + st];
            red[2][tid] += red[2][tid + st];
        }
        __syncthreads();
    }
    if (tid == 0) {
        g_part[blk * 3 + 0] = red[0][0];
        g_part[blk * 3 + 1] = red[1][0];
        g_part[blk * 3 + 2] = red[2][0];
    }
}

// ---------------------------------------------------------------------------
// Kernel 3: single CTA. Final stat reduce -> rep, then MLP with all weights
// staged through shared memory (coalesced loads, bank-padded rows) and
// k-outer loops keeping 8 batch accumulators.
// ---------------------------------------------------------------------------
__global__ __launch_bounds__(256) void k3_mlp(
    const float* __restrict__ Wo1, const float* __restrict__ bo1,   // [256,22],[256]
    const float* __restrict__ Wo2, const float* __restrict__ bo2,   // [128,256],[128]
    const float* __restrict__ Wo3, const float* __restrict__ bo3,   // [64,128],[64]
    float* __restrict__ out)                                        // [8,64]
{
    __shared__ float wtile[128 * 65];   // Wo2 chunk / Wo1 flat / Wo3 padded
    __shared__ float h1s[BB][256];
    __shared__ float h2s[BB][128];
    __shared__ float rep[BB][22];
    const int tid = threadIdx.x;

    // --- final reduce of partial stats -> rep ---
    if (tid < BB) {
        float s2 = 0.f, sc = 0.f, ss = 0.f;
        for (int ch = 0; ch < K2CH; ch++) {
            const int o = (tid * K2CH + ch) * 3;
            s2 += g_part[o + 0];
            sc += g_part[o + 1];
            ss += g_part[o + 2];
        }
        const float inv = 1.f / (fmaxf(sqrtf(s2), 1e-12f) * (float)SDIM);
        const float rm = sc * inv, im = ss * inv;
        for (int q = 0; q < NQ; q++) { rep[tid][q] = rm; rep[tid][NQ + q] = im; }
    }

    // --- layer 1: stage Wo1 (coalesced), 8 batch accumulators ---
    for (int i = tid; i < 256 * 22; i += 256) wtile[i] = Wo1[i];
    __syncthreads();
    {
        float acc[BB];
        const float bias = bo1[tid];
        #pragma unroll
        for (int b = 0; b < BB; b++) acc[b] = bias;
        #pragma unroll
        for (int k = 0; k < 22; k++) {
            const float w = wtile[tid * 22 + k];
            #pragma unroll
            for (int b = 0; b < BB; b++) acc[b] = fmaf(w, rep[b][k], acc[b]);
        }
        #pragma unroll
        for (int b = 0; b < BB; b++) h1s[b][tid] = fmaxf(acc[b], 0.f);
    }

    // --- layer 2: 4 chunks of 64 k-values, Wo2 staged with pad-65 rows ---
    float acc2[BB];
    if (tid < 128) {
        const float bias = bo2[tid];
        #pragma unroll
        for (int b = 0; b < BB; b++) acc2[b] = bias;
    }
    for (int c = 0; c < 4; c++) {
        __syncthreads();   // wtile reuse barrier (also orders h1s writes at c=0)
        for (int i = tid; i < 128 * 64; i += 256) {
            const int o = i >> 6, kk = i & 63;
            wtile[o * 65 + kk] = Wo2[o * 256 + c * 64 + kk];
        }
        __syncthreads();
        if (tid < 128) {
            #pragma unroll 8
            for (int kk = 0; kk < 64; kk++) {
                const float w = wtile[tid * 65 + kk];
                const int kg = c * 64 + kk;
                #pragma unroll
                for (int b = 0; b < BB; b++) acc2[b] = fmaf(w, h1s[b][kg], acc2[b]);
            }
        }
    }
    if (tid < 128) {
        #pragma unroll
        for (int b = 0; b < BB; b++) h2s[b][tid] = fmaxf(acc2[b], 0.f);
    }
    __syncthreads();

    // --- layer 3: Wo3 staged with pad-129 rows ---
    for (int i = tid; i < 64 * 128; i += 256) {
        const int o = i >> 7, k = i & 127;
        wtile[o * 129 + k] = Wo3[i];
    }
    __syncthreads();
    if (tid < 64) {
        float acc3[BB];
        const float bias = bo3[tid];
        #pragma unroll
        for (int b = 0; b < BB; b++) acc3[b] = bias;
        #pragma unroll 8
        for (int k = 0; k < 128; k++) {
            const float w = wtile[tid * 129 + k];
            #pragma unroll
            for (int b = 0; b < BB; b++) acc3[b] = fmaf(w, h2s[b][k], acc3[b]);
        }
        #pragma unroll
        for (int b = 0; b < BB; b++) out[b * 64 + tid] = acc3[b];
    }
}

// ---------------------------------------------------------------------------
extern "C" void kernel_launch(void* const* d_in, const int* in_sizes, int n_in,
                              void* d_out, int out_size)
{
    const float* nf   = (const float*)d_in[0];
    // d_in[1] = edge_indices (int32) — unused by the math
    const float* W1   = (const float*)d_in[2];
    const float* b1   = (const float*)d_in[3];
    const float* W2   = (const float*)d_in[4];
    const float* b2   = (const float*)d_in[5];
    const float* rot  = (const float*)d_in[6];
    const float* ent  = (const float*)d_in[7];
    const float* msg  = (const float*)d_in[8];
    const float* pw   = (const float*)d_in[9];
    const float* Wo1  = (const float*)d_in[10];
    const float* bo1  = (const float*)d_in[11];
    const float* Wo2  = (const float*)d_in[12];
    const float* bo2  = (const float*)d_in[13];
    const float* Wo3  = (const float*)d_in[14];
    const float* bo3  = (const float*)d_in[15];
    float* out = (float*)d_out;

    k1_state<<<NSTATE, 256>>>(nf, W1, b1, W2, b2, rot, ent, pw);
    k2_pool<<<BB * K2CH, 256>>>(msg);
    k3_mlp<<<1, 256>>>(Wo1, bo1, Wo2, bo2, Wo3, bo3, out);
}

// round 10
// speedup vs baseline: 7.1747x; 1.0830x over previous
#include <cuda_runtime.h>
#include <math.h>

#define NQ 11
#define NL 3
#define SDIM 2048          // 2^NQ
#define BB 8
#define AA 96
#define NSTATE (BB*AA)     // 768
#define FDIM 64
#define NG (NL*NQ)         // 33 rotation gates
#define NE (NL*(NQ-1))     // 30 CNOT gates

// Accumulation buffer (no cudaMalloc allowed). Zero-initialized at module load;
// k23 re-zeroes it after reading, so every kernel_launch sees R == 0 on entry.
__device__ float g_R[BB * SDIM];                 // 64 KB pooled real amplitudes

// ---------------------------------------------------------------------------
// Kernel 1: one CTA per state n. Register-resident statevector:
//   layout A: thread tid holds r[k] = amps[(k<<8)|tid] : bits[4:0]=lane,
//             [7:5]=warp, [10:8]=reg k
//   layout B (after smem transpose swapping bits [10:8]<->[7:5]):
//             bits[4:0]=lane (q0-4), [7:5]=reg k (q5-7), [10:8]=warp (q8-10)
// Layer 0's rotation block acts on |0...0> -> product state, computed
// analytically directly in layout B (no shfl, no transpose, no init pass).
// Ends with coalesced atomicAdd of w_a * amps into g_R[b][s].
// ---------------------------------------------------------------------------
__global__ __launch_bounds__(256) void k1_state(
    const float* __restrict__ nf,   // [768,64]
    const float* __restrict__ W1,   // [64,100]
    const float* __restrict__ b1,   // [64]
    const float* __restrict__ W2,   // [11,64]
    const float* __restrict__ b2,   // [11]
    const float* __restrict__ rot,  // [3,11,3] flat
    const float* __restrict__ ent,  // [3,10]
    const float* __restrict__ pw)   // [11]
{
    __shared__ float xbuf[2][SDIM];          // 16KB double-buffered transpose
    __shared__ float hbuf[64];
    __shared__ float f[NQ];
    __shared__ float scc[NG * 3], scs[NG * 3];
    __shared__ float Mg[NG][4];
    __shared__ float pent[NE];
    const int n    = blockIdx.x;
    const int tid  = threadIdx.x;
    const int lane = tid & 31;

    // --- feature preprocessor: h = relu(x @ W1[:, :64]^T + b1) ---
    const float* x = nf + n * FDIM;
    if (tid < 64) {
        float acc = b1[tid];
        const float* w = W1 + tid * 100;
        #pragma unroll 8
        for (int k = 0; k < 64; k++) acc = fmaf(x[k], w[k], acc);
        hbuf[tid] = fmaxf(acc, 0.f);
    }
    __syncthreads();

    if (tid < NQ) {
        float acc = b2[tid];
        const float* w = W2 + tid * 64;
        #pragma unroll 8
        for (int k = 0; k < 64; k++) acc = fmaf(hbuf[k], w[k], acc);
        f[tid] = tanhf(acc);
    }
    __syncthreads();

    // --- (cos,sin) for all 99 (gate,axis) pairs: one per thread ---
    if (tid < NG * 3) {
        const int g = tid / 3;
        const int q = g % NQ;
        float s_, c_;
        __sincosf(0.5f * rot[tid] * f[q], &s_, &c_);
        scc[tid] = c_; scs[tid] = s_;
    }
    __syncthreads();

    // --- gate matrices + CNOT mixing coefficients ---
    if (tid < NG) {
        const float cx = scc[3*tid+0], sx = scs[3*tid+0];
        const float cy = scc[3*tid+1], sy = scs[3*tid+1];
        const float cz = scc[3*tid+2], sz = scs[3*tid+2];
        Mg[tid][0] =  cx * cy * cz;
        Mg[tid][1] = -sx * sy * sz;
        Mg[tid][2] =  sx * sy * cz;
        Mg[tid][3] =  cx * cy * sz;
    } else if (tid >= 64 && tid < 64 + NE) {
        const int e = tid - 64;
        pent[e] = 1.f / (1.f + __expf(-ent[e]));
    }
    __syncthreads();

    const int wbits = (tid >> 5) & 7;             // state bits [7:5] (layout A)
    const int tbase = (wbits << 8) | lane;        // transpose read base

    // === layer 0 rotations, analytic: product of first-column gate entries ===
    // (applied to |0>, every rotation contributes M00 for bit=0, M10 for bit=1)
    // Result constructed directly in LAYOUT B.
    float r[8];
    {
        float laneP = 1.f;
        #pragma unroll
        for (int q = 0; q < 5; q++) laneP *= ((lane >> q) & 1) ? Mg[q][2] : Mg[q][0];
        float wP = 1.f;
        #pragma unroll
        for (int j = 0; j < 3; j++) wP *= ((wbits >> j) & 1) ? Mg[8 + j][2] : Mg[8 + j][0];
        const float lw = laneP * wP;
        #pragma unroll
        for (int k = 0; k < 8; k++) {
            float v = lw;
            #pragma unroll
            for (int j = 0; j < 3; j++) v *= ((k >> j) & 1) ? Mg[5 + j][2] : Mg[5 + j][0];
            r[k] = v;
        }
    }

    for (int l = 0; l < NL; l++) {
        if (l > 0) {
            // ---- rotations on lane qubits 0..4 : shfl_xor (layout A) ----
            #pragma unroll
            for (int q = 0; q < 5; q++) {
                const int g = l * NQ + q;
                const float M00 = Mg[g][0], M01 = Mg[g][1];
                const float M10 = Mg[g][2], M11 = Mg[g][3];
                const int m = 1 << q;
                const bool h = (lane & m) != 0;
                const float co = h ? M11 : M00;
                const float ct = h ? M10 : M01;
                #pragma unroll
                for (int k = 0; k < 8; k++) {
                    const float o = __shfl_xor_sync(0xffffffffu, r[k], m);
                    r[k] = fmaf(co, r[k], ct * o);
                }
            }
            // ---- rotations on register qubits 8,9,10 : pure FMA ----
            #pragma unroll
            for (int j = 0; j < 3; j++) {
                const int g = l * NQ + 8 + j;
                const float M00 = Mg[g][0], M01 = Mg[g][1];
                const float M10 = Mg[g][2], M11 = Mg[g][3];
                #pragma unroll
                for (int k = 0; k < 8; k++) {
                    if (!((k >> j) & 1)) {
                        const int k2 = k | (1 << j);
                        const float a = r[k], b = r[k2];
                        r[k]  = fmaf(M00, a, M01 * b);
                        r[k2] = fmaf(M10, a, M11 * b);
                    }
                }
            }
            // ---- TRANSPOSE A->B: swap state bits [10:8] <-> [7:5] ----
            {
                float* buf = xbuf[0];
                #pragma unroll
                for (int k = 0; k < 8; k++) buf[k * 256 + tid] = r[k];
                __syncthreads();
                #pragma unroll
                for (int k = 0; k < 8; k++) r[k] = buf[tbase + (k << 5)];
            }
            // ---- rotations on qubits 5,6,7 (reg bits in layout B) : FMA ----
            #pragma unroll
            for (int j = 0; j < 3; j++) {
                const int g = l * NQ + 5 + j;
                const float M00 = Mg[g][0], M01 = Mg[g][1];
                const float M10 = Mg[g][2], M11 = Mg[g][3];
                #pragma unroll
                for (int k = 0; k < 8; k++) {
                    if (!((k >> j) & 1)) {
                        const int k2 = k | (1 << j);
                        const float a = r[k], b = r[k2];
                        r[k]  = fmaf(M00, a, M01 * b);
                        r[k2] = fmaf(M10, a, M11 * b);
                    }
                }
            }
        }
        // ---- CNOT chain, in order q = 0..9 (we are in LAYOUT B here) ----
        // q = 0..3 : ctrl lane bit q, comm lane bit q+1 -> shfl
        #pragma unroll
        for (int q = 0; q < 4; q++) {
            const float p = pent[l * (NQ - 1) + q];
            const int m2 = 2 << q;
            const bool c = (lane & (1 << q)) != 0;
            #pragma unroll
            for (int k = 0; k < 8; k++) {
                const float o = __shfl_xor_sync(0xffffffffu, r[k], m2);
                const float mixed = fmaf(p, o - r[k], r[k]);
                r[k] = c ? mixed : r[k];
            }
        }
        // q = 4 : ctrl lane bit 4, comm qubit5 = reg bit 0
        {
            const float p = pent[l * (NQ - 1) + 4];
            if (lane & 16) {
                #pragma unroll
                for (int k = 0; k < 8; k += 2) {
                    const float a = r[k], b = r[k + 1];
                    r[k]     = fmaf(p, b - a, a);
                    r[k + 1] = fmaf(p, a - b, b);
                }
            }
        }
        // q = 5 : ctrl reg bit 0, comm reg bit 1 -> (1,3),(5,7)
        {
            const float p = pent[l * (NQ - 1) + 5];
            { const float a = r[1], b = r[3]; r[1] = fmaf(p, b - a, a); r[3] = fmaf(p, a - b, b); }
            { const float a = r[5], b = r[7]; r[5] = fmaf(p, b - a, a); r[7] = fmaf(p, a - b, b); }
        }
        // q = 6 : ctrl reg bit 1, comm reg bit 2 -> (2,6),(3,7)
        {
            const float p = pent[l * (NQ - 1) + 6];
            { const float a = r[2], b = r[6]; r[2] = fmaf(p, b - a, a); r[6] = fmaf(p, a - b, b); }
            { const float a = r[3], b = r[7]; r[3] = fmaf(p, b - a, a); r[7] = fmaf(p, a - b, b); }
        }
        // ---- TRANSPOSE B->A (involution) ----
        {
            float* buf = xbuf[1];
            #pragma unroll
            for (int k = 0; k < 8; k++) buf[k * 256 + tid] = r[k];
            __syncthreads();
            #pragma unroll
            for (int k = 0; k < 8; k++) r[k] = buf[tbase + (k << 5)];
        }
        // q = 7 : ctrl tid bit 7, comm bit 8 = reg bit 0
        {
            const float p = pent[l * (NQ - 1) + 7];
            if (tid & 128) {
                #pragma unroll
                for (int k = 0; k < 8; k += 2) {
                    const float a = r[k], b = r[k + 1];
                    r[k]     = fmaf(p, b - a, a);
                    r[k + 1] = fmaf(p, a - b, b);
                }
            }
        }
        // q = 8 : ctrl reg bit 0, comm reg bit 1 -> (1,3),(5,7)
        {
            const float p = pent[l * (NQ - 1) + 8];
            { const float a = r[1], b = r[3]; r[1] = fmaf(p, b - a, a); r[3] = fmaf(p, a - b, b); }
            { const float a = r[5], b = r[7]; r[5] = fmaf(p, b - a, a); r[7] = fmaf(p, a - b, b); }
        }
        // q = 9 : ctrl reg bit 1, comm reg bit 2 -> (2,6),(3,7)
        {
            const float p = pent[l * (NQ - 1) + 9];
            { const float a = r[2], b = r[6]; r[2] = fmaf(p, b - a, a); r[6] = fmaf(p, a - b, b); }
            { const float a = r[3], b = r[7]; r[3] = fmaf(p, b - a, a); r[7] = fmaf(p, a - b, b); }
        }
    }

    // --- accumulate pool-weighted amps into R[b][s] (coalesced REDG) ---
    const float wa = 1.f / (1.f + __expf(-pw[(n % AA) % NQ]));
    float* Rb = g_R + (size_t)(n / AA) * SDIM;
    #pragma unroll
    for (int k = 0; k < 8; k++)
        atomicAdd(&Rb[k * 256 + tid], r[k] * wa);
}

// ---------------------------------------------------------------------------
// Kernel 2+3 fused: single CTA, 1024 threads. 128 threads per batch reduce
// R[b][s] into {sumR^2, sumRcos, sumRsin} (and re-zero R for the next graph
// replay), build rep, then run the output MLP (weights staged via smem).
// ---------------------------------------------------------------------------
__global__ __launch_bounds__(1024) void k23_pool_mlp(
    const float* __restrict__ msg,                                  // [3,11,3]
    const float* __restrict__ Wo1, const float* __restrict__ bo1,   // [256,22],[256]
    const float* __restrict__ Wo2, const float* __restrict__ bo2,   // [128,256],[128]
    const float* __restrict__ Wo3, const float* __restrict__ bo3,   // [64,128],[64]
    float* __restrict__ out)                                        // [8,64]
{
    __shared__ float theta[NQ];
    __shared__ float part[BB][4][3];
    __shared__ float rep[BB][22];
    __shared__ float wtile[128 * 65];   // Wo2 chunk / Wo1 flat / Wo3 padded
    __shared__ float h1s[BB][256];
    __shared__ float h2s[BB][128];
    const int tid = threadIdx.x;

    if (tid < NQ) {
        float t = 0.f;
        for (int l = 0; l < NL; l++)
            for (int c = 0; c < 3; c++)
                t += msg[(l * NQ + tid) * 3 + c];
        theta[tid] = t;
    }
    __syncthreads();

    // --- per-batch stats: 128 threads per batch, 16 s-values each ---
    {
        const int b   = tid >> 7;
        const int idx = tid & 127;
        float s2 = 0.f, sc = 0.f, ss = 0.f;
        #pragma unroll
        for (int j = 0; j < 16; j++) {
            const int s = idx + j * 128;
            float* addr = g_R + b * SDIM + s;
            const float R = *addr;
            *addr = 0.f;                         // re-zero for next replay
            float phi = 0.f;
            #pragma unroll
            for (int q = 0; q < NQ; q++) if ((s >> q) & 1) phi += theta[q];
            float cp, sp;
            sincosf(phi, &sp, &cp);              // accurate: phi can be O(10)
            s2 = fmaf(R, R, s2);
            sc = fmaf(R, cp, sc);
            ss = fmaf(R, sp, ss);
        }
        #pragma unroll
        for (int o = 16; o > 0; o >>= 1) {
            s2 += __shfl_xor_sync(0xffffffffu, s2, o);
            sc += __shfl_xor_sync(0xffffffffu, sc, o);
            ss += __shfl_xor_sync(0xffffffffu, ss, o);
        }
        if ((tid & 31) == 0) {
            const int w = (tid >> 5) & 3;
            part[b][w][0] = s2; part[b][w][1] = sc; part[b][w][2] = ss;
        }
    }
    __syncthreads();

    if (tid < BB) {
        float s2 = 0.f, sc = 0.f, ss = 0.f;
        #pragma unroll
        for (int w = 0; w < 4; w++) {
            s2 += part[tid][w][0];
            sc += part[tid][w][1];
            ss += part[tid][w][2];
        }
        const float inv = 1.f / (fmaxf(sqrtf(s2), 1e-12f) * (float)SDIM);
        const float rm = sc * inv, im = ss * inv;
        for (int q = 0; q < NQ; q++) { rep[tid][q] = rm; rep[tid][NQ + q] = im; }
    }

    // --- layer 1: stage Wo1 (coalesced), 8 batch accumulators ---
    for (int i = tid; i < 256 * 22; i += 1024) wtile[i] = Wo1[i];
    __syncthreads();
    if (tid < 256) {
        float acc[BB];
        const float bias = bo1[tid];
        #pragma unroll
        for (int b = 0; b < BB; b++) acc[b] = bias;
        #pragma unroll
        for (int k = 0; k < 22; k++) {
            const float w = wtile[tid * 22 + k];
            #pragma unroll
            for (int b = 0; b < BB; b++) acc[b] = fmaf(w, rep[b][k], acc[b]);
        }
        #pragma unroll
        for (int b = 0; b < BB; b++) h1s[b][tid] = fmaxf(acc[b], 0.f);
    }

    // --- layer 2: 4 chunks of 64 k-values, Wo2 staged with pad-65 rows ---
    float acc2[BB];
    if (tid < 128) {
        const float bias = bo2[tid];
        #pragma unroll
        for (int b = 0; b < BB; b++) acc2[b] = bias;
    }
    for (int c = 0; c < 4; c++) {
        __syncthreads();   // wtile reuse barrier (also orders h1s writes at c=0)
        for (int i = tid; i < 128 * 64; i += 1024) {
            const int o = i >> 6, kk = i & 63;
            wtile[o * 65 + kk] = Wo2[o * 256 + c * 64 + kk];
        }
        __syncthreads();
        if (tid < 128) {
            #pragma unroll 8
            for (int kk = 0; kk < 64; kk++) {
                const float w = wtile[tid * 65 + kk];
                const int kg = c * 64 + kk;
                #pragma unroll
                for (int b = 0; b < BB; b++) acc2[b] = fmaf(w, h1s[b][kg], acc2[b]);
            }
        }
    }
    if (tid < 128) {
        #pragma unroll
        for (int b = 0; b < BB; b++) h2s[b][tid] = fmaxf(acc2[b], 0.f);
    }
    __syncthreads();

    // --- layer 3: Wo3 staged with pad-129 rows ---
    for (int i = tid; i < 64 * 128; i += 1024) {
        const int o = i >> 7, k = i & 127;
        wtile[o * 129 + k] = Wo3[i];
    }
    __syncthreads();
    if (tid < 64) {
        float acc3[BB];
        const float bias = bo3[tid];
        #pragma unroll
        for (int b = 0; b < BB; b++) acc3[b] = bias;
        #pragma unroll 8
        for (int k = 0; k < 128; k++) {
            const float w = wtile[tid * 129 + k];
            #pragma unroll
            for (int b = 0; b < BB; b++) acc3[b] = fmaf(w, h2s[b][k], acc3[b]);
        }
        #pragma unroll
        for (int b = 0; b < BB; b++) out[b * 64 + tid] = acc3[b];
    }
}

// ---------------------------------------------------------------------------
extern "C" void kernel_launch(void* const* d_in, const int* in_sizes, int n_in,
                              void* d_out, int out_size)
{
    const float* nf   = (const float*)d_in[0];
    // d_in[1] = edge_indices (int32) — unused by the math
    const float* W1   = (const float*)d_in[2];
    const float* b1   = (const float*)d_in[3];
    const float* W2   = (const float*)d_in[4];
    const float* b2   = (const float*)d_in[5];
    const float* rot  = (const float*)d_in[6];
    const float* ent  = (const float*)d_in[7];
    const float* msg  = (const float*)d_in[8];
    const float* pw   = (const float*)d_in[9];
    const float* Wo1  = (const float*)d_in[10];
    const float* bo1  = (const float*)d_in[11];
    const float* Wo2  = (const float*)d_in[12];
    const float* bo2  = (const float*)d_in[13];
    const float* Wo3  = (const float*)d_in[14];
    const float* bo3  = (const float*)d_in[15];
    float* out = (float*)d_out;

    k1_state<<<NSTATE, 256>>>(nf, W1, b1, W2, b2, rot, ent, pw);
    k23_pool_mlp<<<1, 1024>>>(msg, Wo1, bo1, Wo2, bo2, Wo3, bo3, out);
}

// round 11
// speedup vs baseline: 7.8801x; 1.0983x over previous
#include <cuda_runtime.h>
#include <math.h>

#define NQ 11
#define NL 3
#define SDIM 2048          // 2^NQ
#define BB 8
#define AA 96
#define NSTATE (BB*AA)     // 768
#define FDIM 64
#define NG (NL*NQ)         // 33 rotation gates
#define NE (NL*(NQ-1))     // 30 CNOT gates

// Accumulation buffer (no cudaMalloc allowed). Zero-initialized at module load;
// k23 re-zeroes it after reading, so every kernel_launch sees R == 0 on entry.
__device__ float g_R[BB * SDIM];                 // 64 KB pooled real amplitudes

// ---------------------------------------------------------------------------
// Kernel 1: one CTA per state n. Register-resident statevector:
//   layout A: thread tid holds r[k] = amps[(k<<8)|tid] : bits[4:0]=lane,
//             [7:5]=warp, [10:8]=reg k
//   layout B (after smem transpose swapping bits [10:8]<->[7:5]):
//             bits[4:0]=lane (q0-4), [7:5]=reg k (q5-7), [10:8]=warp (q8-10)
// Layer 0's rotation block acts on |0...0> -> product state, computed
// analytically directly in layout B. Ends with coalesced atomicAdd of
// w_a * amps into g_R[b][s].
// ---------------------------------------------------------------------------
__global__ __launch_bounds__(256) void k1_state(
    const float* __restrict__ nf,   // [768,64]
    const float* __restrict__ W1,   // [64,100]
    const float* __restrict__ b1,   // [64]
    const float* __restrict__ W2,   // [11,64]
    const float* __restrict__ b2,   // [11]
    const float* __restrict__ rot,  // [3,11,3] flat
    const float* __restrict__ ent,  // [3,10]
    const float* __restrict__ pw)   // [11]
{
    __shared__ float xbuf[2][SDIM];          // 16KB double-buffered transpose
    __shared__ float hbuf[64];
    __shared__ float f[NQ];
    __shared__ float scc[NG * 3], scs[NG * 3];
    __shared__ float Mg[NG][4];
    __shared__ float pent[NE];
    const int n    = blockIdx.x;
    const int tid  = threadIdx.x;
    const int lane = tid & 31;

    // --- feature preprocessor: h = relu(x @ W1[:, :64]^T + b1) ---
    const float* x = nf + n * FDIM;
    if (tid < 64) {
        float acc = b1[tid];
        const float* w = W1 + tid * 100;
        #pragma unroll 8
        for (int k = 0; k < 64; k++) acc = fmaf(x[k], w[k], acc);
        hbuf[tid] = fmaxf(acc, 0.f);
    }
    __syncthreads();

    if (tid < NQ) {
        float acc = b2[tid];
        const float* w = W2 + tid * 64;
        #pragma unroll 8
        for (int k = 0; k < 64; k++) acc = fmaf(hbuf[k], w[k], acc);
        f[tid] = tanhf(acc);
    }
    __syncthreads();

    // --- (cos,sin) for all 99 (gate,axis) pairs: one per thread ---
    if (tid < NG * 3) {
        const int g = tid / 3;
        const int q = g % NQ;
        float s_, c_;
        __sincosf(0.5f * rot[tid] * f[q], &s_, &c_);
        scc[tid] = c_; scs[tid] = s_;
    }
    __syncthreads();

    // --- gate matrices + CNOT mixing coefficients ---
    if (tid < NG) {
        const float cx = scc[3*tid+0], sx = scs[3*tid+0];
        const float cy = scc[3*tid+1], sy = scs[3*tid+1];
        const float cz = scc[3*tid+2], sz = scs[3*tid+2];
        Mg[tid][0] =  cx * cy * cz;
        Mg[tid][1] = -sx * sy * sz;
        Mg[tid][2] =  sx * sy * cz;
        Mg[tid][3] =  cx * cy * sz;
    } else if (tid >= 64 && tid < 64 + NE) {
        const int e = tid - 64;
        pent[e] = 1.f / (1.f + __expf(-ent[e]));
    }
    __syncthreads();

    const int wbits = (tid >> 5) & 7;             // state bits [7:5] (layout A)
    const int tbase = (wbits << 8) | lane;        // transpose read base

    // === layer 0 rotations, analytic (product state from |0>), in LAYOUT B ===
    float r[8];
    {
        float laneP = 1.f;
        #pragma unroll
        for (int q = 0; q < 5; q++) laneP *= ((lane >> q) & 1) ? Mg[q][2] : Mg[q][0];
        float wP = 1.f;
        #pragma unroll
        for (int j = 0; j < 3; j++) wP *= ((wbits >> j) & 1) ? Mg[8 + j][2] : Mg[8 + j][0];
        const float lw = laneP * wP;
        #pragma unroll
        for (int k = 0; k < 8; k++) {
            float v = lw;
            #pragma unroll
            for (int j = 0; j < 3; j++) v *= ((k >> j) & 1) ? Mg[5 + j][2] : Mg[5 + j][0];
            r[k] = v;
        }
    }

    for (int l = 0; l < NL; l++) {
        if (l > 0) {
            // ---- rotations on lane qubits 0..4 : shfl_xor (layout A) ----
            #pragma unroll
            for (int q = 0; q < 5; q++) {
                const int g = l * NQ + q;
                const float M00 = Mg[g][0], M01 = Mg[g][1];
                const float M10 = Mg[g][2], M11 = Mg[g][3];
                const int m = 1 << q;
                const bool h = (lane & m) != 0;
                const float co = h ? M11 : M00;
                const float ct = h ? M10 : M01;
                #pragma unroll
                for (int k = 0; k < 8; k++) {
                    const float o = __shfl_xor_sync(0xffffffffu, r[k], m);
                    r[k] = fmaf(co, r[k], ct * o);
                }
            }
            // ---- rotations on register qubits 8,9,10 : pure FMA ----
            #pragma unroll
            for (int j = 0; j < 3; j++) {
                const int g = l * NQ + 8 + j;
                const float M00 = Mg[g][0], M01 = Mg[g][1];
                const float M10 = Mg[g][2], M11 = Mg[g][3];
                #pragma unroll
                for (int k = 0; k < 8; k++) {
                    if (!((k >> j) & 1)) {
                        const int k2 = k | (1 << j);
                        const float a = r[k], b = r[k2];
                        r[k]  = fmaf(M00, a, M01 * b);
                        r[k2] = fmaf(M10, a, M11 * b);
                    }
                }
            }
            // ---- TRANSPOSE A->B: swap state bits [10:8] <-> [7:5] ----
            {
                float* buf = xbuf[0];
                #pragma unroll
                for (int k = 0; k < 8; k++) buf[k * 256 + tid] = r[k];
                __syncthreads();
                #pragma unroll
                for (int k = 0; k < 8; k++) r[k] = buf[tbase + (k << 5)];
            }
            // ---- rotations on qubits 5,6,7 (reg bits in layout B) : FMA ----
            #pragma unroll
            for (int j = 0; j < 3; j++) {
                const int g = l * NQ + 5 + j;
                const float M00 = Mg[g][0], M01 = Mg[g][1];
                const float M10 = Mg[g][2], M11 = Mg[g][3];
                #pragma unroll
                for (int k = 0; k < 8; k++) {
                    if (!((k >> j) & 1)) {
                        const int k2 = k | (1 << j);
                        const float a = r[k], b = r[k2];
                        r[k]  = fmaf(M00, a, M01 * b);
                        r[k2] = fmaf(M10, a, M11 * b);
                    }
                }
            }
        }
        // ---- CNOT chain, in order q = 0..9 (LAYOUT B here) ----
        #pragma unroll
        for (int q = 0; q < 4; q++) {
            const float p = pent[l * (NQ - 1) + q];
            const int m2 = 2 << q;
            const bool c = (lane & (1 << q)) != 0;
            #pragma unroll
            for (int k = 0; k < 8; k++) {
                const float o = __shfl_xor_sync(0xffffffffu, r[k], m2);
                const float mixed = fmaf(p, o - r[k], r[k]);
                r[k] = c ? mixed : r[k];
            }
        }
        // q = 4 : ctrl lane bit 4, comm qubit5 = reg bit 0
        {
            const float p = pent[l * (NQ - 1) + 4];
            if (lane & 16) {
                #pragma unroll
                for (int k = 0; k < 8; k += 2) {
                    const float a = r[k], b = r[k + 1];
                    r[k]     = fmaf(p, b - a, a);
                    r[k + 1] = fmaf(p, a - b, b);
                }
            }
        }
        // q = 5 : ctrl reg bit 0, comm reg bit 1 -> (1,3),(5,7)
        {
            const float p = pent[l * (NQ - 1) + 5];
            { const float a = r[1], b = r[3]; r[1] = fmaf(p, b - a, a); r[3] = fmaf(p, a - b, b); }
            { const float a = r[5], b = r[7]; r[5] = fmaf(p, b - a, a); r[7] = fmaf(p, a - b, b); }
        }
        // q = 6 : ctrl reg bit 1, comm reg bit 2 -> (2,6),(3,7)
        {
            const float p = pent[l * (NQ - 1) + 6];
            { const float a = r[2], b = r[6]; r[2] = fmaf(p, b - a, a); r[6] = fmaf(p, a - b, b); }
            { const float a = r[3], b = r[7]; r[3] = fmaf(p, b - a, a); r[7] = fmaf(p, a - b, b); }
        }
        // ---- TRANSPOSE B->A (involution) ----
        {
            float* buf = xbuf[1];
            #pragma unroll
            for (int k = 0; k < 8; k++) buf[k * 256 + tid] = r[k];
            __syncthreads();
            #pragma unroll
            for (int k = 0; k < 8; k++) r[k] = buf[tbase + (k << 5)];
        }
        // q = 7 : ctrl tid bit 7, comm bit 8 = reg bit 0
        {
            const float p = pent[l * (NQ - 1) + 7];
            if (tid & 128) {
                #pragma unroll
                for (int k = 0; k < 8; k += 2) {
                    const float a = r[k], b = r[k + 1];
                    r[k]     = fmaf(p, b - a, a);
                    r[k + 1] = fmaf(p, a - b, b);
                }
            }
        }
        // q = 8 : ctrl reg bit 0, comm reg bit 1 -> (1,3),(5,7)
        {
            const float p = pent[l * (NQ - 1) + 8];
            { const float a = r[1], b = r[3]; r[1] = fmaf(p, b - a, a); r[3] = fmaf(p, a - b, b); }
            { const float a = r[5], b = r[7]; r[5] = fmaf(p, b - a, a); r[7] = fmaf(p, a - b, b); }
        }
        // q = 9 : ctrl reg bit 1, comm reg bit 2 -> (2,6),(3,7)
        {
            const float p = pent[l * (NQ - 1) + 9];
            { const float a = r[2], b = r[6]; r[2] = fmaf(p, b - a, a); r[6] = fmaf(p, a - b, b); }
            { const float a = r[3], b = r[7]; r[3] = fmaf(p, b - a, a); r[7] = fmaf(p, a - b, b); }
        }
    }

    // --- accumulate pool-weighted amps into R[b][s] (coalesced REDG) ---
    const float wa = 1.f / (1.f + __expf(-pw[(n % AA) % NQ]));
    float* Rb = g_R + (size_t)(n / AA) * SDIM;
    #pragma unroll
    for (int k = 0; k < 8; k++)
        atomicAdd(&Rb[k * 256 + tid], r[k] * wa);
}

// ---------------------------------------------------------------------------
// Kernel 2+3 fused: single CTA, 1024 threads.
// Stats: phase = exp(i*bits(s).theta) built from 11 base phasors via complex
//        products (NO per-s sincosf). 128 threads per batch, warp reduce.
// MLP: all layers parallelized over 1024 threads via k-split + smem reduce.
// ubuf is a union: weight tile (padded) OR partial-sum buffer.
// ---------------------------------------------------------------------------
#define UBUF_N 8320   // >= 128*65 (Wo2 tile), 64*129 (Wo3), 256*22 (Wo1), 8192 partials

__global__ __launch_bounds__(1024) void k23_pool_mlp(
    const float* __restrict__ msg,                                  // [3,11,3]
    const float* __restrict__ Wo1, const float* __restrict__ bo1,   // [256,22],[256]
    const float* __restrict__ Wo2, const float* __restrict__ bo2,   // [128,256],[128]
    const float* __restrict__ Wo3, const float* __restrict__ bo3,   // [64,128],[64]
    float* __restrict__ out)                                        // [8,64]
{
    __shared__ float ubuf[UBUF_N];      // 33.3KB union buffer
    __shared__ float h1s[BB][256];      // 8KB
    __shared__ float h2s[BB][128];      // 4KB
    __shared__ float rep[BB][22];
    __shared__ float part[BB][4][3];
    __shared__ float phc[NQ], phs[NQ];  // base phasors e^{i theta_q}
    __shared__ float qc[16], qs[16];    // phasor table for state bits 7..10
    const int tid = threadIdx.x;

    // --- base phasors: theta_q = sum_l sum_c msg[l][q][c]; one accurate
    //     sincosf per qubit (11 total in the whole kernel) ---
    if (tid < NQ) {
        float t = 0.f;
        for (int l = 0; l < NL; l++)
            for (int c = 0; c < 3; c++)
                t += msg[(l * NQ + tid) * 3 + c];
        float s_, c_;
        sincosf(t, &s_, &c_);
        phc[tid] = c_; phs[tid] = s_;
    }
    __syncthreads();

    // --- phasor table over bits 7..10 (threads 0..15) ---
    if (tid < 16) {
        float c = 1.f, s = 0.f;
        #pragma unroll
        for (int jb = 0; jb < 4; jb++) {
            if ((tid >> jb) & 1) {
                const float pc = phc[7 + jb], ps = phs[7 + jb];
                const float nc = c * pc - s * ps;
                s = c * ps + s * pc;
                c = nc;
            }
        }
        qc[tid] = c; qs[tid] = s;
    }

    // --- per-thread phasor over bits 0..6 (idx = tid & 127) ---
    const int bq  = tid >> 7;          // batch 0..7
    const int idx = tid & 127;         // state bits [6:0]
    float Pc = 1.f, Ps = 0.f;
    #pragma unroll
    for (int q = 0; q < 7; q++) {
        if ((idx >> q) & 1) {
            const float pc = phc[q], ps = phs[q];
            const float nc = Pc * pc - Ps * ps;
            Ps = Pc * ps + Ps * pc;
            Pc = nc;
        }
    }
    __syncthreads();   // qc/qs visible

    // --- stats: 16 s-values per thread; phase = P * Q[j] (4 FMA each) ---
    {
        float s2 = 0.f, sc = 0.f, ss = 0.f;
        #pragma unroll 4
        for (int j = 0; j < 16; j++) {
            const int s = idx + j * 128;
            float* addr = g_R + bq * SDIM + s;
            const float R = *addr;
            *addr = 0.f;                         // re-zero for next replay
            const float cp = Pc * qc[j] - Ps * qs[j];
            const float sp = Pc * qs[j] + Ps * qc[j];
            s2 = fmaf(R, R, s2);
            sc = fmaf(R, cp, sc);
            ss = fmaf(R, sp, ss);
        }
        #pragma unroll
        for (int o = 16; o > 0; o >>= 1) {
            s2 += __shfl_xor_sync(0xffffffffu, s2, o);
            sc += __shfl_xor_sync(0xffffffffu, sc, o);
            ss += __shfl_xor_sync(0xffffffffu, ss, o);
        }
        if ((tid & 31) == 0) {
            const int w = (tid >> 5) & 3;
            part[bq][w][0] = s2; part[bq][w][1] = sc; part[bq][w][2] = ss;
        }
    }
    __syncthreads();

    if (tid < BB) {
        float s2 = 0.f, sc = 0.f, ss = 0.f;
        #pragma unroll
        for (int w = 0; w < 4; w++) {
            s2 += part[tid][w][0];
            sc += part[tid][w][1];
            ss += part[tid][w][2];
        }
        const float inv = 1.f / (fmaxf(sqrtf(s2), 1e-12f) * (float)SDIM);
        const float rm = sc * inv, im = ss * inv;
        for (int q = 0; q < NQ; q++) { rep[tid][q] = rm; rep[tid][NQ + q] = im; }
    }

    // --- layer 1: stage Wo1 flat into ubuf, 256 threads compute ---
    for (int i = tid; i < 256 * 22; i += 1024) ubuf[i] = Wo1[i];
    __syncthreads();
    if (tid < 256) {
        float acc[BB];
        const float bias = bo1[tid];
        #pragma unroll
        for (int b = 0; b < BB; b++) acc[b] = bias;
        #pragma unroll
        for (int k = 0; k < 22; k++) {
            const float w = ubuf[tid * 22 + k];
            #pragma unroll
            for (int b = 0; b < BB; b++) acc[b] = fmaf(w, rep[b][k], acc[b]);
        }
        #pragma unroll
        for (int b = 0; b < BB; b++) h1s[b][tid] = fmaxf(acc[b], 0.f);
    }

    // --- layer 2: all 1024 threads. thread = (o = tid&127, sub = tid>>7);
    //     sub handles 8 k per 64-chunk; partials reduced via ubuf ---
    {
        const int o   = tid & 127;
        const int sub = tid >> 7;
        float acc2[BB];
        #pragma unroll
        for (int b = 0; b < BB; b++) acc2[b] = 0.f;
        for (int c = 0; c < 4; c++) {
            __syncthreads();   // ubuf reuse (also orders h1s writes at c=0)
            for (int i = tid; i < 128 * 64; i += 1024) {
                const int o2 = i >> 6, kk = i & 63;
                ubuf[o2 * 65 + kk] = Wo2[o2 * 256 + c * 64 + kk];
            }
            __syncthreads();
            #pragma unroll
            for (int kk = 0; kk < 8; kk++) {
                const int kl = sub * 8 + kk;
                const float w = ubuf[o * 65 + kl];
                const int kg = c * 64 + kl;
                #pragma unroll
                for (int b = 0; b < BB; b++) acc2[b] = fmaf(w, h1s[b][kg], acc2[b]);
            }
        }
        __syncthreads();   // all done reading ubuf weight tile
        #pragma unroll
        for (int b = 0; b < BB; b++) ubuf[(sub * 128 + o) * 8 + b] = acc2[b];
    }
    __syncthreads();
    {   // reduce 8 partials per (o,b): thread = (o = tid&127, b = tid>>7)
        const int o = tid & 127;
        const int b = tid >> 7;
        float v = bo2[o];
        #pragma unroll
        for (int sub = 0; sub < 8; sub++) v += ubuf[(sub * 128 + o) * 8 + b];
        h2s[b][o] = fmaxf(v, 0.f);
    }
    __syncthreads();

    // --- layer 3: thread = (o = tid&63, g = tid>>6); g handles 8 k ---
    {
        for (int i = tid; i < 64 * 128; i += 1024) {
            const int o3 = i >> 7, k = i & 127;
            ubuf[o3 * 129 + k] = Wo3[i];
        }
        __syncthreads();
        const int o = tid & 63;
        const int g = tid >> 6;        // 0..15
        float acc3[BB];
        #pragma unroll
        for (int b = 0; b < BB; b++) acc3[b] = 0.f;
        #pragma unroll
        for (int kk = 0; kk < 8; kk++) {
            const int k = g * 8 + kk;
            const float w = ubuf[o * 129 + k];
            #pragma unroll
            for (int b = 0; b < BB; b++) acc3[b] = fmaf(w, h2s[b][k], acc3[b]);
        }
        __syncthreads();   // done reading ubuf weight tile
        #pragma unroll
        for (int b = 0; b < BB; b++) ubuf[(g * 64 + o) * 8 + b] = acc3[b];
    }
    __syncthreads();
    if (tid < 512) {   // reduce 16 partials per (o,b): (b = tid>>6, o = tid&63)
        const int b = tid >> 6;
        const int o = tid & 63;
        float v = bo3[o];
        #pragma unroll
        for (int g = 0; g < 16; g++) v += ubuf[(g * 64 + o) * 8 + b];
        out[b * 64 + o] = v;
    }
}

// ---------------------------------------------------------------------------
extern "C" void kernel_launch(void* const* d_in, const int* in_sizes, int n_in,
                              void* d_out, int out_size)
{
    const float* nf   = (const float*)d_in[0];
    // d_in[1] = edge_indices (int32) — unused by the math
    const float* W1   = (const float*)d_in[2];
    const float* b1   = (const float*)d_in[3];
    const float* W2   = (const float*)d_in[4];
    const float* b2   = (const float*)d_in[5];
    const float* rot  = (const float*)d_in[6];
    const float* ent  = (const float*)d_in[7];
    const float* msg  = (const float*)d_in[8];
    const float* pw   = (const float*)d_in[9];
    const float* Wo1  = (const float*)d_in[10];
    const float* bo1  = (const float*)d_in[11];
    const float* Wo2  = (const float*)d_in[12];
    const float* bo2  = (const float*)d_in[13];
    const float* Wo3  = (const float*)d_in[14];
    const float* bo3  = (const float*)d_in[15];
    float* out = (float*)d_out;

    k1_state<<<NSTATE, 256>>>(nf, W1, b1, W2, b2, rot, ent, pw);
    k23_pool_mlp<<<1, 1024>>>(msg, Wo1, bo1, Wo2, bo2, Wo3, bo3, out);
}

// round 12
// speedup vs baseline: 7.9500x; 1.0089x over previous
#include <cuda_runtime.h>
#include <math.h>

#define NQ 11
#define NL 3
#define SDIM 2048          // 2^NQ
#define BB 8
#define AA 96
#define NSTATE (BB*AA)     // 768
#define FDIM 64
#define NG (NL*NQ)         // 33 rotation gates
#define NE (NL*(NQ-1))     // 30 CNOT gates

// Accumulation buffer (no cudaMalloc allowed). Zero-initialized at module load;
// k23 re-zeroes it after reading, so every kernel_launch sees R == 0 on entry.
__device__ float g_R[BB * SDIM];                 // 64 KB pooled real amplitudes

// ---------------------------------------------------------------------------
// Kernel 1: one CTA per state n. Register-resident statevector (see R9-R11).
// ---------------------------------------------------------------------------
__global__ __launch_bounds__(256) void k1_state(
    const float* __restrict__ nf,   // [768,64]
    const float* __restrict__ W1,   // [64,100]
    const float* __restrict__ b1,   // [64]
    const float* __restrict__ W2,   // [11,64]
    const float* __restrict__ b2,   // [11]
    const float* __restrict__ rot,  // [3,11,3] flat
    const float* __restrict__ ent,  // [3,10]
    const float* __restrict__ pw)   // [11]
{
    __shared__ float xbuf[2][SDIM];          // 16KB double-buffered transpose
    __shared__ float hbuf[64];
    __shared__ float f[NQ];
    __shared__ float scc[NG * 3], scs[NG * 3];
    __shared__ float Mg[NG][4];
    __shared__ float pent[NE];
    const int n    = blockIdx.x;
    const int tid  = threadIdx.x;
    const int lane = tid & 31;

    // --- feature preprocessor: h = relu(x @ W1[:, :64]^T + b1) ---
    const float* x = nf + n * FDIM;
    if (tid < 64) {
        float acc = b1[tid];
        const float* w = W1 + tid * 100;
        #pragma unroll 8
        for (int k = 0; k < 64; k++) acc = fmaf(x[k], w[k], acc);
        hbuf[tid] = fmaxf(acc, 0.f);
    }
    __syncthreads();

    if (tid < NQ) {
        float acc = b2[tid];
        const float* w = W2 + tid * 64;
        #pragma unroll 8
        for (int k = 0; k < 64; k++) acc = fmaf(hbuf[k], w[k], acc);
        f[tid] = tanhf(acc);
    }
    __syncthreads();

    // --- (cos,sin) for all 99 (gate,axis) pairs: one per thread ---
    if (tid < NG * 3) {
        const int g = tid / 3;
        const int q = g % NQ;
        float s_, c_;
        __sincosf(0.5f * rot[tid] * f[q], &s_, &c_);
        scc[tid] = c_; scs[tid] = s_;
    }
    __syncthreads();

    // --- gate matrices + CNOT mixing coefficients ---
    if (tid < NG) {
        const float cx = scc[3*tid+0], sx = scs[3*tid+0];
        const float cy = scc[3*tid+1], sy = scs[3*tid+1];
        const float cz = scc[3*tid+2], sz = scs[3*tid+2];
        Mg[tid][0] =  cx * cy * cz;
        Mg[tid][1] = -sx * sy * sz;
        Mg[tid][2] =  sx * sy * cz;
        Mg[tid][3] =  cx * cy * sz;
    } else if (tid >= 64 && tid < 64 + NE) {
        const int e = tid - 64;
        pent[e] = 1.f / (1.f + __expf(-ent[e]));
    }
    __syncthreads();

    const int wbits = (tid >> 5) & 7;             // state bits [7:5] (layout A)
    const int tbase = (wbits << 8) | lane;        // transpose read base

    // === layer 0 rotations, analytic (product state from |0>), in LAYOUT B ===
    float r[8];
    {
        float laneP = 1.f;
        #pragma unroll
        for (int q = 0; q < 5; q++) laneP *= ((lane >> q) & 1) ? Mg[q][2] : Mg[q][0];
        float wP = 1.f;
        #pragma unroll
        for (int j = 0; j < 3; j++) wP *= ((wbits >> j) & 1) ? Mg[8 + j][2] : Mg[8 + j][0];
        const float lw = laneP * wP;
        #pragma unroll
        for (int k = 0; k < 8; k++) {
            float v = lw;
            #pragma unroll
            for (int j = 0; j < 3; j++) v *= ((k >> j) & 1) ? Mg[5 + j][2] : Mg[5 + j][0];
            r[k] = v;
        }
    }

    for (int l = 0; l < NL; l++) {
        if (l > 0) {
            // ---- rotations on lane qubits 0..4 : shfl_xor (layout A) ----
            #pragma unroll
            for (int q = 0; q < 5; q++) {
                const int g = l * NQ + q;
                const float M00 = Mg[g][0], M01 = Mg[g][1];
                const float M10 = Mg[g][2], M11 = Mg[g][3];
                const int m = 1 << q;
                const bool h = (lane & m) != 0;
                const float co = h ? M11 : M00;
                const float ct = h ? M10 : M01;
                #pragma unroll
                for (int k = 0; k < 8; k++) {
                    const float o = __shfl_xor_sync(0xffffffffu, r[k], m);
                    r[k] = fmaf(co, r[k], ct * o);
                }
            }
            // ---- rotations on register qubits 8,9,10 : pure FMA ----
            #pragma unroll
            for (int j = 0; j < 3; j++) {
                const int g = l * NQ + 8 + j;
                const float M00 = Mg[g][0], M01 = Mg[g][1];
                const float M10 = Mg[g][2], M11 = Mg[g][3];
                #pragma unroll
                for (int k = 0; k < 8; k++) {
                    if (!((k >> j) & 1)) {
                        const int k2 = k | (1 << j);
                        const float a = r[k], b = r[k2];
                        r[k]  = fmaf(M00, a, M01 * b);
                        r[k2] = fmaf(M10, a, M11 * b);
                    }
                }
            }
            // ---- TRANSPOSE A->B: swap state bits [10:8] <-> [7:5] ----
            {
                float* buf = xbuf[0];
                #pragma unroll
                for (int k = 0; k < 8; k++) buf[k * 256 + tid] = r[k];
                __syncthreads();
                #pragma unroll
                for (int k = 0; k < 8; k++) r[k] = buf[tbase + (k << 5)];
            }
            // ---- rotations on qubits 5,6,7 (reg bits in layout B) : FMA ----
            #pragma unroll
            for (int j = 0; j < 3; j++) {
                const int g = l * NQ + 5 + j;
                const float M00 = Mg[g][0], M01 = Mg[g][1];
                const float M10 = Mg[g][2], M11 = Mg[g][3];
                #pragma unroll
                for (int k = 0; k < 8; k++) {
                    if (!((k >> j) & 1)) {
                        const int k2 = k | (1 << j);
                        const float a = r[k], b = r[k2];
                        r[k]  = fmaf(M00, a, M01 * b);
                        r[k2] = fmaf(M10, a, M11 * b);
                    }
                }
            }
        }
        // ---- CNOT chain, in order q = 0..9 (LAYOUT B here) ----
        #pragma unroll
        for (int q = 0; q < 4; q++) {
            const float p = pent[l * (NQ - 1) + q];
            const int m2 = 2 << q;
            const bool c = (lane & (1 << q)) != 0;
            #pragma unroll
            for (int k = 0; k < 8; k++) {
                const float o = __shfl_xor_sync(0xffffffffu, r[k], m2);
                const float mixed = fmaf(p, o - r[k], r[k]);
                r[k] = c ? mixed : r[k];
            }
        }
        // q = 4 : ctrl lane bit 4, comm qubit5 = reg bit 0
        {
            const float p = pent[l * (NQ - 1) + 4];
            if (lane & 16) {
                #pragma unroll
                for (int k = 0; k < 8; k += 2) {
                    const float a = r[k], b = r[k + 1];
                    r[k]     = fmaf(p, b - a, a);
                    r[k + 1] = fmaf(p, a - b, b);
                }
            }
        }
        // q = 5 : (1,3),(5,7)
        {
            const float p = pent[l * (NQ - 1) + 5];
            { const float a = r[1], b = r[3]; r[1] = fmaf(p, b - a, a); r[3] = fmaf(p, a - b, b); }
            { const float a = r[5], b = r[7]; r[5] = fmaf(p, b - a, a); r[7] = fmaf(p, a - b, b); }
        }
        // q = 6 : (2,6),(3,7)
        {
            const float p = pent[l * (NQ - 1) + 6];
            { const float a = r[2], b = r[6]; r[2] = fmaf(p, b - a, a); r[6] = fmaf(p, a - b, b); }
            { const float a = r[3], b = r[7]; r[3] = fmaf(p, b - a, a); r[7] = fmaf(p, a - b, b); }
        }
        // ---- TRANSPOSE B->A (involution) ----
        {
            float* buf = xbuf[1];
            #pragma unroll
            for (int k = 0; k < 8; k++) buf[k * 256 + tid] = r[k];
            __syncthreads();
            #pragma unroll
            for (int k = 0; k < 8; k++) r[k] = buf[tbase + (k << 5)];
        }
        // q = 7 : ctrl tid bit 7, comm reg bit 0
        {
            const float p = pent[l * (NQ - 1) + 7];
            if (tid & 128) {
                #pragma unroll
                for (int k = 0; k < 8; k += 2) {
                    const float a = r[k], b = r[k + 1];
                    r[k]     = fmaf(p, b - a, a);
                    r[k + 1] = fmaf(p, a - b, b);
                }
            }
        }
        // q = 8 : (1,3),(5,7)
        {
            const float p = pent[l * (NQ - 1) + 8];
            { const float a = r[1], b = r[3]; r[1] = fmaf(p, b - a, a); r[3] = fmaf(p, a - b, b); }
            { const float a = r[5], b = r[7]; r[5] = fmaf(p, b - a, a); r[7] = fmaf(p, a - b, b); }
        }
        // q = 9 : (2,6),(3,7)
        {
            const float p = pent[l * (NQ - 1) + 9];
            { const float a = r[2], b = r[6]; r[2] = fmaf(p, b - a, a); r[6] = fmaf(p, a - b, b); }
            { const float a = r[3], b = r[7]; r[3] = fmaf(p, b - a, a); r[7] = fmaf(p, a - b, b); }
        }
    }

    // --- accumulate pool-weighted amps into R[b][s] (coalesced REDG) ---
    const float wa = 1.f / (1.f + __expf(-pw[(n % AA) % NQ]));
    float* Rb = g_R + (size_t)(n / AA) * SDIM;
    #pragma unroll
    for (int k = 0; k < 8; k++)
        atomicAdd(&Rb[k * 256 + tid], r[k] * wa);
}

// ---------------------------------------------------------------------------
// Kernel 2+3 fused v2: single CTA, 1024 threads, ~183 KB DYNAMIC smem.
// ALL weights staged into smem up front (one overlapped burst, g_R loads
// issued first so their latency hides under staging). Every later phase is
// smem-only -> phase cost ~ barrier latency, not memory latency.
// Wo2 smem region is reused as the partial-sum buffer after its last read.
// ---------------------------------------------------------------------------
#define W1S_OFF 0                        // 256*22 = 5632 floats (flat)
#define W2S_OFF 5632                     // 128 rows * pad 257 = 32896
#define W3S_OFF (5632 + 32896)           // 64 rows * pad 129 = 8256
#define DYN_FLOATS (W1S_OFF + 5632 + 32896 + 8256)
#define DYN_BYTES  (DYN_FLOATS * 4)      // 187,136 B

extern __shared__ float dsm[];

__global__ __launch_bounds__(1024) void k23_pool_mlp(
    const float* __restrict__ msg,                                  // [3,11,3]
    const float* __restrict__ Wo1, const float* __restrict__ bo1,   // [256,22],[256]
    const float* __restrict__ Wo2, const float* __restrict__ bo2,   // [128,256],[128]
    const float* __restrict__ Wo3, const float* __restrict__ bo3,   // [64,128],[64]
    float* __restrict__ out)                                        // [8,64]
{
    __shared__ float h1s[BB][256];      // 8KB
    __shared__ float h2s[BB][128];      // 4KB
    __shared__ float rep[BB][22];
    __shared__ float part[BB][4][3];
    __shared__ float phc[NQ], phs[NQ];
    __shared__ float qc[16], qs[16];
    float* w1s = dsm + W1S_OFF;
    float* w2s = dsm + W2S_OFF;
    float* w3s = dsm + W3S_OFF;
    float* psum = dsm + W2S_OFF;        // partial buffer reuses Wo2 region
    const int tid = threadIdx.x;
    const int bq  = tid >> 7;           // batch 0..7
    const int idx = tid & 127;          // state bits [6:0]

    // === 1. issue g_R loads FIRST (latency hides under weight staging) ===
    float Rv[16];
    {
        float* base = g_R + bq * SDIM + idx;
        #pragma unroll
        for (int j = 0; j < 16; j++) Rv[j] = base[j * 128];
        #pragma unroll
        for (int j = 0; j < 16; j++) base[j * 128] = 0.f;   // re-zero for next replay
    }

    // === 2. stage ALL weights into smem (one burst, ~46 LDG/thread) ===
    for (int i = tid; i < 256 * 22; i += 1024) w1s[i] = Wo1[i];
    for (int i = tid; i < 128 * 256; i += 1024) {
        const int o = i >> 8, k = i & 255;
        w2s[o * 257 + k] = Wo2[i];
    }
    for (int i = tid; i < 64 * 128; i += 1024) {
        const int o = i >> 7, k = i & 127;
        w3s[o * 129 + k] = Wo3[i];
    }

    // === 3. phasors: 11 accurate sincosf total ===
    if (tid < NQ) {
        float t = 0.f;
        for (int l = 0; l < NL; l++)
            for (int c = 0; c < 3; c++)
                t += msg[(l * NQ + tid) * 3 + c];
        float s_, c_;
        sincosf(t, &s_, &c_);
        phc[tid] = c_; phs[tid] = s_;
    }
    __syncthreads();
    if (tid < 16) {                      // phasor table for bits 7..10
        float c = 1.f, s = 0.f;
        #pragma unroll
        for (int jb = 0; jb < 4; jb++) {
            if ((tid >> jb) & 1) {
                const float pc = phc[7 + jb], ps = phs[7 + jb];
                const float nc = c * pc - s * ps;
                s = c * ps + s * pc;
                c = nc;
            }
        }
        qc[tid] = c; qs[tid] = s;
    }
    float Pc = 1.f, Ps = 0.f;            // per-thread phasor over bits 0..6
    #pragma unroll
    for (int q = 0; q < 7; q++) {
        if ((idx >> q) & 1) {
            const float pc = phc[q], ps = phs[q];
            const float nc = Pc * pc - Ps * ps;
            Ps = Pc * ps + Ps * pc;
            Pc = nc;
        }
    }
    __syncthreads();                     // qc/qs visible; staging also done

    // === 4. stats: 16 s-values per thread; phase = P * Q[j] ===
    {
        float s2 = 0.f, sc = 0.f, ss = 0.f;
        #pragma unroll
        for (int j = 0; j < 16; j++) {
            const float R  = Rv[j];
            const float cp = Pc * qc[j] - Ps * qs[j];
            const float sp = Pc * qs[j] + Ps * qc[j];
            s2 = fmaf(R, R, s2);
            sc = fmaf(R, cp, sc);
            ss = fmaf(R, sp, ss);
        }
        #pragma unroll
        for (int o = 16; o > 0; o >>= 1) {
            s2 += __shfl_xor_sync(0xffffffffu, s2, o);
            sc += __shfl_xor_sync(0xffffffffu, sc, o);
            ss += __shfl_xor_sync(0xffffffffu, ss, o);
        }
        if ((tid & 31) == 0) {
            const int w = (tid >> 5) & 3;
            part[bq][w][0] = s2; part[bq][w][1] = sc; part[bq][w][2] = ss;
        }
    }
    __syncthreads();

    if (tid < BB) {
        float s2 = 0.f, sc = 0.f, ss = 0.f;
        #pragma unroll
        for (int w = 0; w < 4; w++) {
            s2 += part[tid][w][0];
            sc += part[tid][w][1];
            ss += part[tid][w][2];
        }
        const float inv = 1.f / (fmaxf(sqrtf(s2), 1e-12f) * (float)SDIM);
        const float rm = sc * inv, im = ss * inv;
        for (int q = 0; q < NQ; q++) { rep[tid][q] = rm; rep[tid][NQ + q] = im; }
    }
    __syncthreads();

    // === 5. layer 1: 256 threads, all-smem ===
    if (tid < 256) {
        float acc[BB];
        const float bias = bo1[tid];
        #pragma unroll
        for (int b = 0; b < BB; b++) acc[b] = bias;
        #pragma unroll
        for (int k = 0; k < 22; k++) {
            const float w = w1s[tid * 22 + k];
            #pragma unroll
            for (int b = 0; b < BB; b++) acc[b] = fmaf(w, rep[b][k], acc[b]);
        }
        #pragma unroll
        for (int b = 0; b < BB; b++) h1s[b][tid] = fmaxf(acc[b], 0.f);
    }
    __syncthreads();

    // === 6. layer 2: (o = tid&127, sub = tid>>7); 32 k each, all-smem ===
    {
        const int o   = tid & 127;
        const int sub = tid >> 7;
        float acc2[BB];
        #pragma unroll
        for (int b = 0; b < BB; b++) acc2[b] = 0.f;
        #pragma unroll 8
        for (int kk = 0; kk < 32; kk++) {
            const int kl = sub * 32 + kk;            // uniform per warp -> h1s broadcast
            const float w = w2s[o * 257 + kl];
            #pragma unroll
            for (int b = 0; b < BB; b++) acc2[b] = fmaf(w, h1s[b][kl], acc2[b]);
        }
        __syncthreads();                             // last read of w2s tile
        #pragma unroll
        for (int b = 0; b < BB; b++) psum[(sub * 128 + o) * 8 + b] = acc2[b];
    }
    __syncthreads();
    {   // reduce 8 partials per (o,b): (o = tid&127, b = tid>>7)
        const int o = tid & 127;
        const int b = tid >> 7;
        float v = bo2[o];
        #pragma unroll
        for (int sub = 0; sub < 8; sub++) v += psum[(sub * 128 + o) * 8 + b];
        h2s[b][o] = fmaxf(v, 0.f);
    }
    __syncthreads();

    // === 7. layer 3: (o = tid&63, g = tid>>6); 8 k each, all-smem ===
    {
        const int o = tid & 63;
        const int g = tid >> 6;                      // 0..15
        float acc3[BB];
        #pragma unroll
        for (int b = 0; b < BB; b++) acc3[b] = 0.f;
        #pragma unroll
        for (int kk = 0; kk < 8; kk++) {
            const int k = g * 8 + kk;                // uniform per warp -> h2s broadcast
            const float w = w3s[o * 129 + k];
            #pragma unroll
            for (int b = 0; b < BB; b++) acc3[b] = fmaf(w, h2s[b][k], acc3[b]);
        }
        __syncthreads();                             // psum region free again
        #pragma unroll
        for (int b = 0; b < BB; b++) psum[(g * 64 + o) * 8 + b] = acc3[b];
    }
    __syncthreads();
    if (tid < 512) {   // reduce 16 partials per (o,b): (b = tid>>6, o = tid&63)
        const int b = tid >> 6;
        const int o = tid & 63;
        float v = bo3[o];
        #pragma unroll
        for (int g = 0; g < 16; g++) v += psum[(g * 64 + o) * 8 + b];
        out[b * 64 + o] = v;
    }
}

// ---------------------------------------------------------------------------
extern "C" void kernel_launch(void* const* d_in, const int* in_sizes, int n_in,
                              void* d_out, int out_size)
{
    const float* nf   = (const float*)d_in[0];
    // d_in[1] = edge_indices (int32) — unused by the math
    const float* W1   = (const float*)d_in[2];
    const float* b1   = (const float*)d_in[3];
    const float* W2   = (const float*)d_in[4];
    const float* b2   = (const float*)d_in[5];
    const float* rot  = (const float*)d_in[6];
    const float* ent  = (const float*)d_in[7];
    const float* msg  = (const float*)d_in[8];
    const float* pw   = (const float*)d_in[9];
    const float* Wo1  = (const float*)d_in[10];
    const float* bo1  = (const float*)d_in[11];
    const float* Wo2  = (const float*)d_in[12];
    const float* bo2  = (const float*)d_in[13];
    const float* Wo3  = (const float*)d_in[14];
    const float* bo3  = (const float*)d_in[15];
    float* out = (float*)d_out;

    // Allow >48KB dynamic smem for k23 (host API, not a stream op; safe to
    // call on every capture — replays don't re-run host code).
    cudaFuncSetAttribute(k23_pool_mlp,
                         cudaFuncAttributeMaxDynamicSharedMemorySize, DYN_BYTES);

    k1_state<<<NSTATE, 256>>>(nf, W1, b1, W2, b2, rot, ent, pw);
    k23_pool_mlp<<<1, 1024, DYN_BYTES>>>(msg, Wo1, bo1, Wo2, bo2, Wo3, bo3, out);
}